// round 4
// baseline (speedup 1.0000x reference)
#include <cuda_runtime.h>

#define Bv 8
#define Sv 100
#define Tv 1200
#define NMELv 80
#define DMv 128
#define KKv 9

typedef unsigned long long u64;

// Scratch (no cudaMalloc allowed)
__device__ float g_x[Bv * Tv * NMELv];          // conv output, 3.07 MB
__device__ float g_xg[Bv * Tv * 768];           // GRU input projections, 29.5 MB

__device__ __forceinline__ float sigmoidf_fast(float x) {
    return __fdividef(1.f, 1.f + __expf(-x));
}
__device__ __forceinline__ float tanhf_fast(float x) {
    return 1.f - __fdividef(2.f, __expf(2.f * x) + 1.f);
}

// ---- packed f32x2 helpers (Blackwell sm_103a) ----
__device__ __forceinline__ u64 pk2(float lo, float hi) {
    u64 r; asm("mov.b64 %0, {%1, %2};" : "=l"(r) : "f"(lo), "f"(hi)); return r;
}
__device__ __forceinline__ void up2(u64 v, float& lo, float& hi) {
    asm("mov.b64 {%0, %1}, %2;" : "=f"(lo), "=f"(hi) : "l"(v));
}
__device__ __forceinline__ u64 fma2(u64 a, u64 b, u64 c) {
    u64 d; asm("fma.rn.f32x2 %0, %1, %2, %3;" : "=l"(d) : "l"(a), "l"(b), "l"(c)); return d;
}
__device__ __forceinline__ u64 add2(u64 a, u64 b) {
    u64 d; asm("add.rn.f32x2 %0, %1, %2;" : "=l"(d) : "l"(a), "l"(b)); return d;
}

#define PSW 134   // conv partial-row stride in u64 (1072 B, 16B-aligned rows)
#define WSW 132   // gru W row stride in floats (528 B, 16B-aligned rows, conflict-free)

// ---------------------------------------------------------------------------
// Kernel 1: fused conv stack, register-resident, f32x2 packed.
// __launch_bounds__(128, 2) -> reg cap 256 -> no spills.
// 128 threads = 128 channels. Pair layout: (m, m+40).
// ---------------------------------------------------------------------------
__global__ __launch_bounds__(128, 2) void conv_kernel(
    const float* __restrict__ mel, const int* __restrict__ mel_len,
    const float* __restrict__ w1, const float* __restrict__ g1, const float* __restrict__ be1,
    const float* __restrict__ w2, const float* __restrict__ g2, const float* __restrict__ be2)
{
    int bt = blockIdx.x;
    int b = bt / Tv, t = bt - b * Tv;
    if (t >= mel_len[b]) return;

    extern __shared__ __align__(16) float sm[];
    u64* ps2 = (u64*)sm;                   // [40][PSW] packed partials
    u64* mp2 = ps2 + 40 * PSW;             // 48 packed mel pairs
    int c = threadIdx.x;

    // Packed, padded mel: M[j] = mel[j-4] for j in [4,84), else 0. mp2[j]=(M[j],M[j+40])
    if (c < 48) {
        float lo = (c >= 4) ? mel[bt * NMELv + c - 4] : 0.f;
        float hi = (c < 44) ? mel[bt * NMELv + c + 36] : 0.f;
        mp2[c] = pk2(lo, hi);
    }

    // Weights with BN scales folded in
    float sc1c = g1[c] * rsqrtf(1.f + 1e-5f);
    float bb1c = be1[c];
    float s2   = g2[0] * rsqrtf(1.f + 1e-5f);
    u64 w1p[KKv], w2p[KKv];
    #pragma unroll
    for (int k = 0; k < KKv; k++) {
        float a = w1[c * KKv + k] * sc1c;  w1p[k] = pk2(a, a);
        float d = w2[c * KKv + k] * s2;    w2p[k] = pk2(d, d);
    }
    u64 bbp = pk2(bb1c, bb1c);
    __syncthreads();

    // conv1 with sliding register window over mel pairs
    u64 Yp[48];
    u64 ring[9];
    #pragma unroll
    for (int j = 0; j < 8; j++) ring[j] = mp2[j];
    #pragma unroll
    for (int m = 0; m < 40; m++) {
        ring[(m + 8) % 9] = mp2[m + 8];
        u64 acc = bbp;
        #pragma unroll
        for (int k = 0; k < KKv; k++) acc = fma2(w1p[k], ring[(m + k) % 9], acc);
        float a, h; up2(acc, a, h);
        Yp[m + 4] = pk2(fmaxf(a, 0.f), fmaxf(h, 0.f));
    }
    // Edge pairs: Yp[j]=(0, lo(Yp[40+j])), Yp[44+j]=(hi(Yp[4+j]), 0)
    #pragma unroll
    for (int j = 0; j < 4; j++) {
        float a, h;
        up2(Yp[40 + j], a, h); Yp[j]      = pk2(0.f, a);
        up2(Yp[4 + j],  a, h); Yp[44 + j] = pk2(h, 0.f);
    }

    // conv2 per-channel contribution -> packed partials (one STS.64 per m-pair)
    #pragma unroll
    for (int m = 0; m < 40; m++) {
        u64 acc = 0ull;
        #pragma unroll
        for (int k = 0; k < KKv; k++) acc = fma2(w2p[k], Yp[m + k], acc);
        ps2[m * PSW + c] = acc;
    }
    __syncthreads();

    // Cross-channel reduction: thread j<40 sums 128 packed partials -> outputs (j, j+40)
    if (c < 40) {
        const ulonglong2* row = (const ulonglong2*)(ps2 + c * PSW);
        u64 s0 = 0ull, s1 = 0ull;
        #pragma unroll
        for (int q = 0; q < 32; q++) {
            ulonglong2 v0 = row[2 * q];
            ulonglong2 v1 = row[2 * q + 1];
            s0 = add2(s0, add2(v0.x, v0.y));
            s1 = add2(s1, add2(v1.x, v1.y));
        }
        u64 tot = add2(s0, s1);
        float a, h; up2(tot, a, h);
        float bb2 = be2[0];
        g_x[bt * NMELv + c]      = fmaxf(a + bb2, 0.f);
        g_x[bt * NMELv + c + 40] = fmaxf(h + bb2, 0.f);
    }
}

// ---------------------------------------------------------------------------
// Kernel 2: input projection GEMM, f32x2 packed over frame pairs. (unchanged)
// ---------------------------------------------------------------------------
__global__ __launch_bounds__(256) void proj_kernel(
    const float* __restrict__ w_ih_f, const float* __restrict__ b_ih_f,
    const float* __restrict__ w_ih_b, const float* __restrict__ b_ih_b)
{
    int f0 = blockIdx.x * 64;
    int g0 = blockIdx.y * 128;
    extern __shared__ float sm[];
    float* Xs = sm;             // [80][66]
    float* Ws = sm + 80 * 66;   // [80][129]
    int tid = threadIdx.x;

    for (int i = tid; i < 64 * NMELv; i += 256) {
        int r = i / NMELv, m = i - r * NMELv;
        Xs[m * 66 + r] = g_x[(f0 + r) * NMELv + m];
    }
    const float* wsrc = (g0 < 384) ? (w_ih_f + g0 * NMELv) : (w_ih_b + (g0 - 384) * NMELv);
    const float* bsrc = (g0 < 384) ? (b_ih_f + g0) : (b_ih_b + (g0 - 384));
    for (int i = tid; i < 128 * NMELv; i += 256) {
        int cc = i / NMELv, m = i - cc * NMELv;
        Ws[m * 129 + cc] = wsrc[cc * NMELv + m];
    }
    __syncthreads();

    int tx = tid & 15, ty = tid >> 4;
    u64 acc[8][2];
    #pragma unroll
    for (int u = 0; u < 8; u++) { acc[u][0] = 0ull; acc[u][1] = 0ull; }

    #pragma unroll 4
    for (int m = 0; m < NMELv; m++) {
        u64 x0 = *(const u64*)&Xs[m * 66 + ty * 4];
        u64 x1 = *(const u64*)&Xs[m * 66 + ty * 4 + 2];
        #pragma unroll
        for (int u = 0; u < 8; u++) {
            float wv = Ws[m * 129 + tx + 16 * u];
            u64 wp = pk2(wv, wv);
            acc[u][0] = fma2(wp, x0, acc[u][0]);
            acc[u][1] = fma2(wp, x1, acc[u][1]);
        }
    }
    #pragma unroll
    for (int u = 0; u < 8; u++) {
        int cc = tx + 16 * u;
        float bias = bsrc[cc];
        float a0, a1, a2, a3;
        up2(acc[u][0], a0, a1);
        up2(acc[u][1], a2, a3);
        int base = (f0 + ty * 4) * 768 + g0 + cc;
        g_xg[base]            = a0 + bias;
        g_xg[base + 768]      = a1 + bias;
        g_xg[base + 2 * 768]  = a2 + bias;
        g_xg[base + 3 * 768]  = a3 + bias;
    }
}

// ---------------------------------------------------------------------------
// Kernel 3: segment GRU v3. W in SMEM (row stride WSW=132 -> 16B-aligned,
// conflict-free LDS.128), h as [k][8-batch] u64 pairs. 8 batches/block, grid 200.
// ---------------------------------------------------------------------------
__global__ void __launch_bounds__(384, 1) gru_kernel(
    const int* __restrict__ durations, const int* __restrict__ src_len,
    const float* __restrict__ w_hh_f, const float* __restrict__ b_hh_f,
    const float* __restrict__ w_hh_b, const float* __restrict__ b_hh_b,
    float* __restrict__ out)
{
    int blk = blockIdx.x;               // 0..199
    int dir = blk / Sv;
    int s = blk - dir * Sv;
    int g = threadIdx.x;

    extern __shared__ __align__(16) float smg[];
    float* Wt    = smg;                                   // [384][WSW]
    u64*   h8    = (u64*)(Wt + 384 * WSW);                // [128][4] batch pairs
    float* gate_s= (float*)(h8 + 128 * 4);                // [8][256]
    float* hn_s  = gate_s + 8 * 256;                      // [8][128]
    float* xn_s  = hn_s + 8 * 128;                        // [8][128]
    int*   meta  = (int*)(xn_s + 8 * 128);                // start[8], dur[8], maxd

    const float* whh = dir ? w_hh_b : w_hh_f;
    for (int idx = g; idx < 384 * 128; idx += 384) {
        int gg = idx >> 7, k = idx & 127;
        Wt[gg * WSW + k] = whh[idx];
    }
    if (g < 8) {
        int st = 0;
        for (int ss = 0; ss < s; ss++) st += durations[g * Sv + ss];
        meta[g] = st;
        meta[8 + g] = durations[g * Sv + s];
    }
    for (int i = g; i < 128 * 4 * 2; i += 384) ((float*)h8)[i] = 0.f;
    __syncthreads();
    if (g == 0) {
        int mx = 0;
        for (int bb = 0; bb < 8; bb++) mx = max(mx, meta[8 + bb]);
        meta[16] = mx;
    }
    __syncthreads();

    float bias_g = (dir ? b_hh_b : b_hh_f)[g];
    int maxd = meta[16];
    int st[8], du[8];
    #pragma unroll
    for (int bb = 0; bb < 8; bb++) { st[bb] = meta[bb]; du[bb] = meta[8 + bb]; }
    const float* xgb = g_xg + dir * 384 + g;
    const float* wrow = Wt + g * WSW;

    for (int i = 0; i < maxd; i++) {
        // prefetch x projections (8 independent LDGs, consumed after matvec)
        float xv[8];
        #pragma unroll
        for (int bb = 0; bb < 8; bb++) {
            int d = du[bb];
            int ie = min(i, d - 1);
            int t = st[bb] + (dir ? (d - 1 - ie) : ie);
            xv[bb] = xgb[(bb * Tv + t) * 768];
        }
        u64 acc0 = pk2(bias_g, bias_g), acc1 = acc0, acc2 = acc0, acc3 = acc0;
        #pragma unroll 8
        for (int k4 = 0; k4 < 32; k4++) {
            float4 wq = *(const float4*)(wrow + 4 * k4);
            float wk[4] = {wq.x, wq.y, wq.z, wq.w};
            #pragma unroll
            for (int j = 0; j < 4; j++) {
                int k = 4 * k4 + j;
                u64 wp = pk2(wk[j], wk[j]);
                ulonglong2 p0 = *((const ulonglong2*)(h8 + k * 4));
                ulonglong2 p1 = *((const ulonglong2*)(h8 + k * 4 + 2));
                acc0 = fma2(wp, p0.x, acc0);
                acc1 = fma2(wp, p0.y, acc1);
                acc2 = fma2(wp, p1.x, acc2);
                acc3 = fma2(wp, p1.y, acc3);
            }
        }
        float accf[8];
        up2(acc0, accf[0], accf[1]);
        up2(acc1, accf[2], accf[3]);
        up2(acc2, accf[4], accf[5]);
        up2(acc3, accf[6], accf[7]);

        if (g < 256) {
            #pragma unroll
            for (int bb = 0; bb < 8; bb++)
                gate_s[bb * 256 + g] = sigmoidf_fast(xv[bb] + accf[bb]);   // r, z
        } else {
            int j = g - 256;
            #pragma unroll
            for (int bb = 0; bb < 8; bb++) {
                hn_s[bb * 128 + j] = accf[bb];
                xn_s[bb * 128 + j] = xv[bb];
            }
        }
        __syncthreads();
        if (g < 128) {
            ulonglong2 hp0 = *((ulonglong2*)(h8 + g * 4));
            ulonglong2 hp1 = *((ulonglong2*)(h8 + g * 4 + 2));
            float ho[8];
            up2(hp0.x, ho[0], ho[1]); up2(hp0.y, ho[2], ho[3]);
            up2(hp1.x, ho[4], ho[5]); up2(hp1.y, ho[6], ho[7]);
            float hnew[8];
            #pragma unroll
            for (int bb = 0; bb < 8; bb++) {
                float rr = gate_s[bb * 256 + g];
                float zz = gate_s[bb * 256 + 128 + g];
                float n = tanhf_fast(fmaf(rr, hn_s[bb * 128 + g], xn_s[bb * 128 + g]));
                float hv = fmaf(zz, ho[bb] - n, n);          // (1-z)*n + z*h
                hnew[bb] = (i < du[bb]) ? hv : ho[bb];       // freeze after segment
            }
            hp0.x = pk2(hnew[0], hnew[1]); hp0.y = pk2(hnew[2], hnew[3]);
            hp1.x = pk2(hnew[4], hnew[5]); hp1.y = pk2(hnew[6], hnew[7]);
            *((ulonglong2*)(h8 + g * 4))     = hp0;
            *((ulonglong2*)(h8 + g * 4 + 2)) = hp1;
        }
        __syncthreads();
    }

    if (g < 128) {
        float hf[8];
        ulonglong2 hp0 = *((ulonglong2*)(h8 + g * 4));
        ulonglong2 hp1 = *((ulonglong2*)(h8 + g * 4 + 2));
        up2(hp0.x, hf[0], hf[1]); up2(hp0.y, hf[2], hf[3]);
        up2(hp1.x, hf[4], hf[5]); up2(hp1.y, hf[6], hf[7]);
        #pragma unroll
        for (int bb = 0; bb < 8; bb++) {
            float v = (s < src_len[bb]) ? hf[bb] : 0.f;
            out[(bb * Sv + s) * 256 + dir * 128 + g] = v;
        }
    }
}

// ---------------------------------------------------------------------------
extern "C" void kernel_launch(void* const* d_in, const int* in_sizes, int n_in,
                              void* d_out, int out_size) {
    const float* mel      = (const float*)d_in[0];
    const int*   durations= (const int*)d_in[1];
    const int*   mel_len  = (const int*)d_in[2];
    const int*   src_len  = (const int*)d_in[3];
    const float* w1       = (const float*)d_in[4];
    const float* g1       = (const float*)d_in[5];
    const float* be1      = (const float*)d_in[6];
    const float* w2       = (const float*)d_in[7];
    const float* g2       = (const float*)d_in[8];
    const float* be2      = (const float*)d_in[9];
    const float* w_ih_f   = (const float*)d_in[10];
    const float* w_hh_f   = (const float*)d_in[11];
    const float* b_ih_f   = (const float*)d_in[12];
    const float* b_hh_f   = (const float*)d_in[13];
    const float* w_ih_b   = (const float*)d_in[14];
    const float* w_hh_b   = (const float*)d_in[15];
    const float* b_ih_b   = (const float*)d_in[16];
    const float* b_hh_b   = (const float*)d_in[17];
    float* out = (float*)d_out;

    size_t conv_smem = (size_t)(40 * PSW + 48) * sizeof(u64);
    size_t proj_smem = (size_t)(80 * 66 + 80 * 129) * sizeof(float);
    size_t gru_smem  = (size_t)(384 * WSW) * sizeof(float) + 128 * 4 * sizeof(u64)
                     + (8 * 256 + 8 * 128 + 8 * 128) * sizeof(float) + 32 * sizeof(int);
    cudaFuncSetAttribute(conv_kernel, cudaFuncAttributeMaxDynamicSharedMemorySize, (int)conv_smem);
    cudaFuncSetAttribute(proj_kernel, cudaFuncAttributeMaxDynamicSharedMemorySize, (int)proj_smem);
    cudaFuncSetAttribute(gru_kernel,  cudaFuncAttributeMaxDynamicSharedMemorySize, (int)gru_smem);

    conv_kernel<<<Bv * Tv, 128, conv_smem>>>(mel, mel_len, w1, g1, be1, w2, g2, be2);
    proj_kernel<<<dim3(150, 6), 256, proj_smem>>>(w_ih_f, b_ih_f, w_ih_b, b_ih_b);
    gru_kernel<<<200, 384, gru_smem>>>(durations, src_len, w_hh_f, b_hh_f, w_hh_b, b_hh_b, out);
}

// round 5
// speedup vs baseline: 1.0668x; 1.0668x over previous
#include <cuda_runtime.h>

#define Bv 8
#define Sv 100
#define Tv 1200
#define NMELv 80
#define DMv 128
#define KKv 9

typedef unsigned long long u64;

// Scratch (no cudaMalloc allowed)
__device__ float g_x[Bv * Tv * NMELv];          // conv output, 3.07 MB
__device__ float g_xg[Bv * Tv * 768];           // GRU input projections, 29.5 MB

__device__ __forceinline__ float sigmoidf_fast(float x) {
    return __fdividef(1.f, 1.f + __expf(-x));
}
__device__ __forceinline__ float tanhf_fast(float x) {
    return 1.f - __fdividef(2.f, __expf(2.f * x) + 1.f);
}

// ---- packed f32x2 helpers (Blackwell sm_103a) ----
__device__ __forceinline__ u64 pk2(float lo, float hi) {
    u64 r; asm("mov.b64 %0, {%1, %2};" : "=l"(r) : "f"(lo), "f"(hi)); return r;
}
__device__ __forceinline__ void up2(u64 v, float& lo, float& hi) {
    asm("mov.b64 {%0, %1}, %2;" : "=f"(lo), "=f"(hi) : "l"(v));
}
__device__ __forceinline__ u64 fma2(u64 a, u64 b, u64 c) {
    u64 d; asm("fma.rn.f32x2 %0, %1, %2, %3;" : "=l"(d) : "l"(a), "l"(b), "l"(c)); return d;
}
__device__ __forceinline__ u64 add2(u64 a, u64 b) {
    u64 d; asm("add.rn.f32x2 %0, %1, %2;" : "=l"(d) : "l"(a), "l"(b)); return d;
}

#define PSW 134   // conv partial-row stride in u64 (1072 B, 16B-aligned rows)
#define WSW 132   // gru W row stride in floats (528 B, 16B-aligned rows, conflict-free)

// ---------------------------------------------------------------------------
// Kernel 1: fused conv stack, f32x2 packed.
// __launch_bounds__(128, 4): cap 128 regs -> small spills but 16 warps/SM.
// (Round 4 evidence: 196 regs / 8 warps was latency-bound at issue=38%.)
// ---------------------------------------------------------------------------
__global__ __launch_bounds__(128, 4) void conv_kernel(
    const float* __restrict__ mel, const int* __restrict__ mel_len,
    const float* __restrict__ w1, const float* __restrict__ g1, const float* __restrict__ be1,
    const float* __restrict__ w2, const float* __restrict__ g2, const float* __restrict__ be2)
{
    int bt = blockIdx.x;
    int b = bt / Tv, t = bt - b * Tv;
    if (t >= mel_len[b]) return;

    extern __shared__ __align__(16) float sm[];
    u64* ps2 = (u64*)sm;                   // [40][PSW] packed partials
    u64* mp2 = ps2 + 40 * PSW;             // 48 packed mel pairs
    int c = threadIdx.x;

    // Packed, padded mel: M[j] = mel[j-4] for j in [4,84), else 0. mp2[j]=(M[j],M[j+40])
    if (c < 48) {
        float lo = (c >= 4) ? mel[bt * NMELv + c - 4] : 0.f;
        float hi = (c < 44) ? mel[bt * NMELv + c + 36] : 0.f;
        mp2[c] = pk2(lo, hi);
    }

    // Weights with BN scales folded in
    float sc1c = g1[c] * rsqrtf(1.f + 1e-5f);
    float bb1c = be1[c];
    float s2   = g2[0] * rsqrtf(1.f + 1e-5f);
    u64 w1p[KKv], w2p[KKv];
    #pragma unroll
    for (int k = 0; k < KKv; k++) {
        float a = w1[c * KKv + k] * sc1c;  w1p[k] = pk2(a, a);
        float d = w2[c * KKv + k] * s2;    w2p[k] = pk2(d, d);
    }
    u64 bbp = pk2(bb1c, bb1c);
    __syncthreads();

    // conv1 with sliding register window over mel pairs
    u64 Yp[48];
    u64 ring[9];
    #pragma unroll
    for (int j = 0; j < 8; j++) ring[j] = mp2[j];
    #pragma unroll
    for (int m = 0; m < 40; m++) {
        ring[(m + 8) % 9] = mp2[m + 8];
        u64 acc = bbp;
        #pragma unroll
        for (int k = 0; k < KKv; k++) acc = fma2(w1p[k], ring[(m + k) % 9], acc);
        float a, h; up2(acc, a, h);
        Yp[m + 4] = pk2(fmaxf(a, 0.f), fmaxf(h, 0.f));
    }
    // Edge pairs: Yp[j]=(0, lo(Yp[40+j])), Yp[44+j]=(hi(Yp[4+j]), 0)
    #pragma unroll
    for (int j = 0; j < 4; j++) {
        float a, h;
        up2(Yp[40 + j], a, h); Yp[j]      = pk2(0.f, a);
        up2(Yp[4 + j],  a, h); Yp[44 + j] = pk2(h, 0.f);
    }

    // conv2 per-channel contribution -> packed partials (one STS.64 per m-pair)
    #pragma unroll
    for (int m = 0; m < 40; m++) {
        u64 acc = 0ull;
        #pragma unroll
        for (int k = 0; k < KKv; k++) acc = fma2(w2p[k], Yp[m + k], acc);
        ps2[m * PSW + c] = acc;
    }
    __syncthreads();

    // Cross-channel reduction: thread j<40 sums 128 packed partials -> outputs (j, j+40)
    if (c < 40) {
        const ulonglong2* row = (const ulonglong2*)(ps2 + c * PSW);
        u64 s0 = 0ull, s1 = 0ull;
        #pragma unroll
        for (int q = 0; q < 32; q++) {
            ulonglong2 v0 = row[2 * q];
            ulonglong2 v1 = row[2 * q + 1];
            s0 = add2(s0, add2(v0.x, v0.y));
            s1 = add2(s1, add2(v1.x, v1.y));
        }
        u64 tot = add2(s0, s1);
        float a, h; up2(tot, a, h);
        float bb2 = be2[0];
        g_x[bt * NMELv + c]      = fmaxf(a + bb2, 0.f);
        g_x[bt * NMELv + c + 40] = fmaxf(h + bb2, 0.f);
    }
}

// ---------------------------------------------------------------------------
// Kernel 2: input projection GEMM, f32x2 packed over frame pairs. (unchanged)
// ---------------------------------------------------------------------------
__global__ __launch_bounds__(256) void proj_kernel(
    const float* __restrict__ w_ih_f, const float* __restrict__ b_ih_f,
    const float* __restrict__ w_ih_b, const float* __restrict__ b_ih_b)
{
    int f0 = blockIdx.x * 64;
    int g0 = blockIdx.y * 128;
    extern __shared__ float sm[];
    float* Xs = sm;             // [80][66]
    float* Ws = sm + 80 * 66;   // [80][129]
    int tid = threadIdx.x;

    for (int i = tid; i < 64 * NMELv; i += 256) {
        int r = i / NMELv, m = i - r * NMELv;
        Xs[m * 66 + r] = g_x[(f0 + r) * NMELv + m];
    }
    const float* wsrc = (g0 < 384) ? (w_ih_f + g0 * NMELv) : (w_ih_b + (g0 - 384) * NMELv);
    const float* bsrc = (g0 < 384) ? (b_ih_f + g0) : (b_ih_b + (g0 - 384));
    for (int i = tid; i < 128 * NMELv; i += 256) {
        int cc = i / NMELv, m = i - cc * NMELv;
        Ws[m * 129 + cc] = wsrc[cc * NMELv + m];
    }
    __syncthreads();

    int tx = tid & 15, ty = tid >> 4;
    u64 acc[8][2];
    #pragma unroll
    for (int u = 0; u < 8; u++) { acc[u][0] = 0ull; acc[u][1] = 0ull; }

    #pragma unroll 4
    for (int m = 0; m < NMELv; m++) {
        u64 x0 = *(const u64*)&Xs[m * 66 + ty * 4];
        u64 x1 = *(const u64*)&Xs[m * 66 + ty * 4 + 2];
        #pragma unroll
        for (int u = 0; u < 8; u++) {
            float wv = Ws[m * 129 + tx + 16 * u];
            u64 wp = pk2(wv, wv);
            acc[u][0] = fma2(wp, x0, acc[u][0]);
            acc[u][1] = fma2(wp, x1, acc[u][1]);
        }
    }
    #pragma unroll
    for (int u = 0; u < 8; u++) {
        int cc = tx + 16 * u;
        float bias = bsrc[cc];
        float a0, a1, a2, a3;
        up2(acc[u][0], a0, a1);
        up2(acc[u][1], a2, a3);
        int base = (f0 + ty * 4) * 768 + g0 + cc;
        g_xg[base]            = a0 + bias;
        g_xg[base + 768]      = a1 + bias;
        g_xg[base + 2 * 768]  = a2 + bias;
        g_xg[base + 3 * 768]  = a3 + bias;
    }
}

// ---------------------------------------------------------------------------
// Kernel 3: segment GRU. W in SMEM (stride WSW=132: 16B-aligned, conflict-free
// LDS.128). Duration starts via WARP SHFL PREFIX SCAN (was: up to 99 serial
// dependent-latency LDG iterations gating the whole block through syncthreads).
// ---------------------------------------------------------------------------
__global__ void __launch_bounds__(384, 1) gru_kernel(
    const int* __restrict__ durations, const int* __restrict__ src_len,
    const float* __restrict__ w_hh_f, const float* __restrict__ b_hh_f,
    const float* __restrict__ w_hh_b, const float* __restrict__ b_hh_b,
    float* __restrict__ out)
{
    int blk = blockIdx.x;               // 0..199
    int dir = blk / Sv;
    int s = blk - dir * Sv;
    int g = threadIdx.x;

    extern __shared__ __align__(16) float smg[];
    float* Wt    = smg;                                   // [384][WSW]
    u64*   h8    = (u64*)(Wt + 384 * WSW);                // [128][4] batch pairs
    float* gate_s= (float*)(h8 + 128 * 4);                // [8][256]
    float* hn_s  = gate_s + 8 * 256;                      // [8][128]
    float* xn_s  = hn_s + 8 * 128;                        // [8][128]
    int*   meta  = (int*)(xn_s + 8 * 128);                // start[8], dur[8], maxd

    const float* whh = dir ? w_hh_b : w_hh_f;
    for (int idx = g; idx < 384 * 128; idx += 384) {
        int gg = idx >> 7, k = idx & 127;
        Wt[gg * WSW + k] = whh[idx];
    }

    // Parallel prefix scan: warp w < 8 scans durations row b=w in 32-chunks.
    {
        int wid = g >> 5, lane = g & 31;
        if (wid < 8) {
            int b = wid;
            int carry = 0;
            #pragma unroll
            for (int c0 = 0; c0 < 128; c0 += 32) {
                int ss = c0 + lane;
                int d = (ss < Sv) ? durations[b * Sv + ss] : 0;
                int v = d;
                #pragma unroll
                for (int off = 1; off < 32; off <<= 1) {
                    int n = __shfl_up_sync(0xFFFFFFFFu, v, off);
                    if (lane >= off) v += n;
                }
                if (ss == s) { meta[b] = carry + v - d; meta[8 + b] = d; }
                carry += __shfl_sync(0xFFFFFFFFu, v, 31);
            }
        }
    }
    for (int i = g; i < 128 * 4 * 2; i += 384) ((float*)h8)[i] = 0.f;
    __syncthreads();
    if (g == 0) {
        int mx = 0;
        for (int bb = 0; bb < 8; bb++) mx = max(mx, meta[8 + bb]);
        meta[16] = mx;
    }
    __syncthreads();

    float bias_g = (dir ? b_hh_b : b_hh_f)[g];
    int maxd = meta[16];
    int st[8], du[8];
    #pragma unroll
    for (int bb = 0; bb < 8; bb++) { st[bb] = meta[bb]; du[bb] = meta[8 + bb]; }
    const float* xgb = g_xg + dir * 384 + g;
    const float* wrow = Wt + g * WSW;

    for (int i = 0; i < maxd; i++) {
        // prefetch x projections (8 independent LDGs, consumed after matvec)
        float xv[8];
        #pragma unroll
        for (int bb = 0; bb < 8; bb++) {
            int d = du[bb];
            int ie = min(i, d - 1);
            int t = st[bb] + (dir ? (d - 1 - ie) : ie);
            xv[bb] = xgb[(bb * Tv + t) * 768];
        }
        u64 acc0 = pk2(bias_g, bias_g), acc1 = acc0, acc2 = acc0, acc3 = acc0;
        #pragma unroll 8
        for (int k4 = 0; k4 < 32; k4++) {
            float4 wq = *(const float4*)(wrow + 4 * k4);
            float wk[4] = {wq.x, wq.y, wq.z, wq.w};
            #pragma unroll
            for (int j = 0; j < 4; j++) {
                int k = 4 * k4 + j;
                u64 wp = pk2(wk[j], wk[j]);
                ulonglong2 p0 = *((const ulonglong2*)(h8 + k * 4));
                ulonglong2 p1 = *((const ulonglong2*)(h8 + k * 4 + 2));
                acc0 = fma2(wp, p0.x, acc0);
                acc1 = fma2(wp, p0.y, acc1);
                acc2 = fma2(wp, p1.x, acc2);
                acc3 = fma2(wp, p1.y, acc3);
            }
        }
        float accf[8];
        up2(acc0, accf[0], accf[1]);
        up2(acc1, accf[2], accf[3]);
        up2(acc2, accf[4], accf[5]);
        up2(acc3, accf[6], accf[7]);

        if (g < 256) {
            #pragma unroll
            for (int bb = 0; bb < 8; bb++)
                gate_s[bb * 256 + g] = sigmoidf_fast(xv[bb] + accf[bb]);   // r, z
        } else {
            int j = g - 256;
            #pragma unroll
            for (int bb = 0; bb < 8; bb++) {
                hn_s[bb * 128 + j] = accf[bb];
                xn_s[bb * 128 + j] = xv[bb];
            }
        }
        __syncthreads();
        if (g < 128) {
            ulonglong2 hp0 = *((ulonglong2*)(h8 + g * 4));
            ulonglong2 hp1 = *((ulonglong2*)(h8 + g * 4 + 2));
            float ho[8];
            up2(hp0.x, ho[0], ho[1]); up2(hp0.y, ho[2], ho[3]);
            up2(hp1.x, ho[4], ho[5]); up2(hp1.y, ho[6], ho[7]);
            float hnew[8];
            #pragma unroll
            for (int bb = 0; bb < 8; bb++) {
                float rr = gate_s[bb * 256 + g];
                float zz = gate_s[bb * 256 + 128 + g];
                float n = tanhf_fast(fmaf(rr, hn_s[bb * 128 + g], xn_s[bb * 128 + g]));
                float hv = fmaf(zz, ho[bb] - n, n);          // (1-z)*n + z*h
                hnew[bb] = (i < du[bb]) ? hv : ho[bb];       // freeze after segment
            }
            hp0.x = pk2(hnew[0], hnew[1]); hp0.y = pk2(hnew[2], hnew[3]);
            hp1.x = pk2(hnew[4], hnew[5]); hp1.y = pk2(hnew[6], hnew[7]);
            *((ulonglong2*)(h8 + g * 4))     = hp0;
            *((ulonglong2*)(h8 + g * 4 + 2)) = hp1;
        }
        __syncthreads();
    }

    if (g < 128) {
        float hf[8];
        ulonglong2 hp0 = *((ulonglong2*)(h8 + g * 4));
        ulonglong2 hp1 = *((ulonglong2*)(h8 + g * 4 + 2));
        up2(hp0.x, hf[0], hf[1]); up2(hp0.y, hf[2], hf[3]);
        up2(hp1.x, hf[4], hf[5]); up2(hp1.y, hf[6], hf[7]);
        #pragma unroll
        for (int bb = 0; bb < 8; bb++) {
            float v = (s < src_len[bb]) ? hf[bb] : 0.f;
            out[(bb * Sv + s) * 256 + dir * 128 + g] = v;
        }
    }
}

// ---------------------------------------------------------------------------
extern "C" void kernel_launch(void* const* d_in, const int* in_sizes, int n_in,
                              void* d_out, int out_size) {
    const float* mel      = (const float*)d_in[0];
    const int*   durations= (const int*)d_in[1];
    const int*   mel_len  = (const int*)d_in[2];
    const int*   src_len  = (const int*)d_in[3];
    const float* w1       = (const float*)d_in[4];
    const float* g1       = (const float*)d_in[5];
    const float* be1      = (const float*)d_in[6];
    const float* w2       = (const float*)d_in[7];
    const float* g2       = (const float*)d_in[8];
    const float* be2      = (const float*)d_in[9];
    const float* w_ih_f   = (const float*)d_in[10];
    const float* w_hh_f   = (const float*)d_in[11];
    const float* b_ih_f   = (const float*)d_in[12];
    const float* b_hh_f   = (const float*)d_in[13];
    const float* w_ih_b   = (const float*)d_in[14];
    const float* w_hh_b   = (const float*)d_in[15];
    const float* b_ih_b   = (const float*)d_in[16];
    const float* b_hh_b   = (const float*)d_in[17];
    float* out = (float*)d_out;

    size_t conv_smem = (size_t)(40 * PSW + 48) * sizeof(u64);
    size_t proj_smem = (size_t)(80 * 66 + 80 * 129) * sizeof(float);
    size_t gru_smem  = (size_t)(384 * WSW) * sizeof(float) + 128 * 4 * sizeof(u64)
                     + (8 * 256 + 8 * 128 + 8 * 128) * sizeof(float) + 32 * sizeof(int);
    cudaFuncSetAttribute(conv_kernel, cudaFuncAttributeMaxDynamicSharedMemorySize, (int)conv_smem);
    cudaFuncSetAttribute(proj_kernel, cudaFuncAttributeMaxDynamicSharedMemorySize, (int)proj_smem);
    cudaFuncSetAttribute(gru_kernel,  cudaFuncAttributeMaxDynamicSharedMemorySize, (int)gru_smem);

    conv_kernel<<<Bv * Tv, 128, conv_smem>>>(mel, mel_len, w1, g1, be1, w2, g2, be2);
    proj_kernel<<<dim3(150, 6), 256, proj_smem>>>(w_ih_f, b_ih_f, w_ih_b, b_ih_b);
    gru_kernel<<<200, 384, gru_smem>>>(durations, src_len, w_hh_f, b_hh_f, w_hh_b, b_hh_b, out);
}

// round 6
// speedup vs baseline: 1.2038x; 1.1284x over previous
#include <cuda_runtime.h>

#define Bv 8
#define Sv 100
#define Tv 1200
#define NMELv 80
#define DMv 128
#define KKv 9

typedef unsigned long long u64;

// Scratch (no cudaMalloc allowed)
__device__ float g_x[Bv * Tv * NMELv];          // conv output, 3.07 MB
__device__ float g_xg[Bv * Tv * 768];           // GRU input projections, 29.5 MB

__device__ __forceinline__ float sigmoidf_fast(float x) {
    return __fdividef(1.f, 1.f + __expf(-x));
}
__device__ __forceinline__ float tanhf_fast(float x) {
    return 1.f - __fdividef(2.f, __expf(2.f * x) + 1.f);
}

// ---- packed f32x2 helpers (Blackwell sm_103a) ----
__device__ __forceinline__ u64 pk2(float lo, float hi) {
    u64 r; asm("mov.b64 %0, {%1, %2};" : "=l"(r) : "f"(lo), "f"(hi)); return r;
}
__device__ __forceinline__ void up2(u64 v, float& lo, float& hi) {
    asm("mov.b64 {%0, %1}, %2;" : "=f"(lo), "=f"(hi) : "l"(v));
}
__device__ __forceinline__ u64 fma2(u64 a, u64 b, u64 c) {
    u64 d; asm("fma.rn.f32x2 %0, %1, %2, %3;" : "=l"(d) : "l"(a), "l"(b), "l"(c)); return d;
}
__device__ __forceinline__ u64 add2(u64 a, u64 b) {
    u64 d; asm("add.rn.f32x2 %0, %1, %2;" : "=l"(d) : "l"(a), "l"(b)); return d;
}

#define PSW 134   // conv partial-row stride in u64 (1072 B, 16B-aligned rows)
#define WSW 132   // gru W row stride in floats (528 B, 16B-aligned rows)
#define PWW 130   // proj packed-W row stride in u64 (1040 B, 16B-aligned rows)

// ---------------------------------------------------------------------------
// Kernel 1: fused conv stack, STREAMING conv2 (9-slot acc ring fused into the
// conv1 sweep) -> ~90 live regs, no spills at (128,4), 16 warps/SM.
// 128 threads = 128 channels. Pair layout: (m, m+40).
// ---------------------------------------------------------------------------
__global__ __launch_bounds__(128, 4) void conv_kernel(
    const float* __restrict__ mel, const int* __restrict__ mel_len,
    const float* __restrict__ w1, const float* __restrict__ g1, const float* __restrict__ be1,
    const float* __restrict__ w2, const float* __restrict__ g2, const float* __restrict__ be2)
{
    int bt = blockIdx.x;
    int b = bt / Tv, t = bt - b * Tv;
    if (t >= mel_len[b]) return;

    extern __shared__ __align__(16) float sm[];
    u64* ps2 = (u64*)sm;                   // [40][PSW] packed partials
    u64* mp2 = ps2 + 40 * PSW;             // 48 packed mel pairs
    int c = threadIdx.x;

    // Packed, padded mel: M[j] = mel[j-4] for j in [4,84), else 0. mp2[j]=(M[j],M[j+40])
    if (c < 48) {
        float lo = (c >= 4) ? mel[bt * NMELv + c - 4] : 0.f;
        float hi = (c < 44) ? mel[bt * NMELv + c + 36] : 0.f;
        mp2[c] = pk2(lo, hi);
    }

    // Weights with BN scales folded in
    float sc1c = g1[c] * rsqrtf(1.f + 1e-5f);
    float bb1c = be1[c];
    float s2   = g2[0] * rsqrtf(1.f + 1e-5f);
    float w1f[KKv];
    u64 w2p[KKv];
    #pragma unroll
    for (int k = 0; k < KKv; k++) {
        w1f[k] = w1[c * KKv + k] * sc1c;
        float d = w2[c * KKv + k] * s2;    w2p[k] = pk2(d, d);
    }
    __syncthreads();

    // Head: Y[36..39] scalar (needed for edge pairs Yp[0..3] = (0, Y[36+e]))
    float head[4];
    #pragma unroll
    for (int e = 0; e < 4; e++) {
        float acc = bb1c;
        #pragma unroll
        for (int k = 0; k < KKv; k++) {
            float lo, hi; up2(mp2[36 + e + k], lo, hi);
            acc = fmaf(w1f[k], lo, acc);
        }
        head[e] = fmaxf(acc, 0.f);
    }

    // Pack conv1 weights
    u64 w1p[KKv];
    #pragma unroll
    for (int k = 0; k < KKv; k++) w1p[k] = pk2(w1f[k], w1f[k]);
    u64 bbp = pk2(bb1c, bb1c);

    // Accumulator ring: A[m % 9] accumulates conv2 output pair m (m = 0..39)
    u64 A[9];
    #pragma unroll
    for (int q = 0; q < 9; q++) A[q] = 0ull;

    // Seed with edge pairs Yp[j] = (0, head[j]), j = 0..3: A[m] += w2p[j-m]*Ypj, m<=j
    #pragma unroll
    for (int j = 0; j < 4; j++) {
        u64 yp = pk2(0.f, head[j]);
        #pragma unroll
        for (int m = 0; m <= j; m++) A[m] = fma2(w2p[j - m], yp, A[m]);
    }

    // Stream j = 4..47: conv1 pair -> conv2 ring updates -> completion stores
    u64 ring[9];
    #pragma unroll
    for (int q = 0; q < 8; q++) ring[q] = mp2[q];
    float sv[4];   // hi lanes of Yp[4..7] = Y[40..43] (for edge pairs Yp[44..47])

    #pragma unroll
    for (int j = 4; j < 48; j++) {
        u64 yp;
        if (j < 44) {
            ring[(j + 4) % 9] = mp2[j + 4];
            u64 acc = bbp;
            #pragma unroll
            for (int k = 0; k < KKv; k++) acc = fma2(w1p[k], ring[(j - 4 + k) % 9], acc);
            float a, h; up2(acc, a, h);
            a = fmaxf(a, 0.f); h = fmaxf(h, 0.f);
            if (j < 8) sv[j - 4] = h;
            yp = pk2(a, h);
        } else {
            yp = pk2(sv[j - 44], 0.f);
        }
        #pragma unroll
        for (int k = 0; k < KKv; k++) {
            int m = j - k;
            if (m >= 0 && m <= 39) A[m % 9] = fma2(w2p[k], yp, A[m % 9]);
        }
        int md = j - 8;
        if (md >= 0 && md <= 39) {
            ps2[md * PSW + c] = A[md % 9];
            A[md % 9] = 0ull;
        }
    }
    __syncthreads();

    // Cross-channel reduction: thread j<40 sums 128 packed partials -> outputs (j, j+40)
    if (c < 40) {
        const ulonglong2* row = (const ulonglong2*)(ps2 + c * PSW);
        u64 s0 = 0ull, s1 = 0ull;
        #pragma unroll
        for (int q = 0; q < 32; q++) {
            ulonglong2 v0 = row[2 * q];
            ulonglong2 v1 = row[2 * q + 1];
            s0 = add2(s0, add2(v0.x, v0.y));
            s1 = add2(s1, add2(v1.x, v1.y));
        }
        u64 tot = add2(s0, s1);
        float a, h; up2(tot, a, h);
        float bb2 = be2[0];
        g_x[bt * NMELv + c]      = fmaxf(a + bb2, 0.f);
        g_x[bt * NMELv + c + 40] = fmaxf(h + bb2, 0.f);
    }
}

// ---------------------------------------------------------------------------
// Kernel 2: input projection GEMM. W pre-packed in smem as duplicate f32 pairs
// (u64) -> no per-iteration pk2, LDS.64 per gate. 2 blocks/SM (104 KB smem).
// ---------------------------------------------------------------------------
__global__ __launch_bounds__(256) void proj_kernel(
    const float* __restrict__ w_ih_f, const float* __restrict__ b_ih_f,
    const float* __restrict__ w_ih_b, const float* __restrict__ b_ih_b)
{
    int f0 = blockIdx.x * 64;
    int g0 = blockIdx.y * 128;
    extern __shared__ __align__(16) char smc[];
    u64*   Ws2 = (u64*)smc;                  // [80][PWW] duplicated pairs
    float* Xs  = (float*)(Ws2 + 80 * PWW);   // [80][66]
    int tid = threadIdx.x;

    for (int i = tid; i < 64 * NMELv; i += 256) {
        int r = i / NMELv, m = i - r * NMELv;
        Xs[m * 66 + r] = g_x[(f0 + r) * NMELv + m];
    }
    const float* wsrc = (g0 < 384) ? (w_ih_f + g0 * NMELv) : (w_ih_b + (g0 - 384) * NMELv);
    const float* bsrc = (g0 < 384) ? (b_ih_f + g0) : (b_ih_b + (g0 - 384));
    for (int i = tid; i < 128 * NMELv; i += 256) {
        int cc = i / NMELv, m = i - cc * NMELv;     // i = cc*80+m -> coalesced LDG
        float v = wsrc[i];
        Ws2[m * PWW + cc] = pk2(v, v);
    }
    __syncthreads();

    int tx = tid & 15, ty = tid >> 4;   // 8 gates x (2 frame-pairs) per thread
    u64 acc[8][2];
    #pragma unroll
    for (int u = 0; u < 8; u++) { acc[u][0] = 0ull; acc[u][1] = 0ull; }

    #pragma unroll 4
    for (int m = 0; m < NMELv; m++) {
        u64 x0 = *(const u64*)&Xs[m * 66 + ty * 4];
        u64 x1 = *(const u64*)&Xs[m * 66 + ty * 4 + 2];
        #pragma unroll
        for (int u = 0; u < 8; u++) {
            u64 wp = Ws2[m * PWW + tx + 16 * u];
            acc[u][0] = fma2(wp, x0, acc[u][0]);
            acc[u][1] = fma2(wp, x1, acc[u][1]);
        }
    }
    #pragma unroll
    for (int u = 0; u < 8; u++) {
        int cc = tx + 16 * u;
        float bias = bsrc[cc];
        float a0, a1, a2, a3;
        up2(acc[u][0], a0, a1);
        up2(acc[u][1], a2, a3);
        int base = (f0 + ty * 4) * 768 + g0 + cc;
        g_xg[base]            = a0 + bias;
        g_xg[base + 768]      = a1 + bias;
        g_xg[base + 2 * 768]  = a2 + bias;
        g_xg[base + 3 * 768]  = a3 + bias;
    }
}

// ---------------------------------------------------------------------------
// Kernel 3: segment GRU v5 — gate-local threads.
// 128 threads; thread g owns W rows {g, 128+g, 256+g} (r/z/n of hidden unit g)
// -> gates computed entirely in registers, no smem gate exchange.
// 4 chains/block (one (dir, s, b-half)), grid 400. W in smem.
// ---------------------------------------------------------------------------
__global__ void __launch_bounds__(128, 1) gru_kernel(
    const int* __restrict__ durations, const int* __restrict__ src_len,
    const float* __restrict__ w_hh_f, const float* __restrict__ b_hh_f,
    const float* __restrict__ w_hh_b, const float* __restrict__ b_hh_b,
    float* __restrict__ out)
{
    int blk = blockIdx.x;               // 0..399
    int dir = blk / 200;
    int r = blk - dir * 200;
    int s = r >> 1, b0 = (r & 1) * 4;
    int g = threadIdx.x;                // 0..127

    extern __shared__ __align__(16) float smg[];
    float* Wt   = smg;                               // [384][WSW]
    u64*   h2   = (u64*)(Wt + 384 * WSW);            // [128][2] chain pairs
    int*   meta = (int*)(h2 + 128 * 2);              // start[4], dur[4]

    // Load W (vectorized): row-major, padded stride WSW
    const float* whh = dir ? w_hh_b : w_hh_f;
    {
        const float4* src = (const float4*)whh;
        for (int i = g; i < 384 * 32; i += 128) {
            int row = i >> 5, q = i & 31;
            *(float4*)&Wt[row * WSW + 4 * q] = src[i];
        }
    }
    // Warp w scans durations row (b0 + w) for segment start/duration
    {
        int wid = g >> 5, lane = g & 31;
        int b = b0 + wid;
        int carry = 0;
        #pragma unroll
        for (int c0 = 0; c0 < 128; c0 += 32) {
            int ss = c0 + lane;
            int d = (ss < Sv) ? durations[b * Sv + ss] : 0;
            int v = d;
            #pragma unroll
            for (int off = 1; off < 32; off <<= 1) {
                int n = __shfl_up_sync(0xFFFFFFFFu, v, off);
                if (lane >= off) v += n;
            }
            if (ss == s) { meta[wid] = carry + v - d; meta[4 + wid] = d; }
            carry += __shfl_sync(0xFFFFFFFFu, v, 31);
        }
    }
    h2[g * 2] = 0ull; h2[g * 2 + 1] = 0ull;
    __syncthreads();

    int st[4], du[4];
    #pragma unroll
    for (int cb = 0; cb < 4; cb++) { st[cb] = meta[cb]; du[cb] = meta[4 + cb]; }
    int maxd = max(max(du[0], du[1]), max(du[2], du[3]));

    const float* bhh = dir ? b_hh_b : b_hh_f;
    float br = bhh[g], bz = bhh[128 + g], bn = bhh[256 + g];
    const float* wr = Wt + g * WSW;
    const float* wz = Wt + (128 + g) * WSW;
    const float* wn = Wt + (256 + g) * WSW;
    const float* xbase = g_xg + dir * 384;

    float hold[4] = {0.f, 0.f, 0.f, 0.f};

    for (int i = 0; i < maxd; i++) {
        // x projections: 3 gates x 4 chains (independent LDGs, hidden under matvec)
        float xr[4], xz[4], xn[4];
        #pragma unroll
        for (int cb = 0; cb < 4; cb++) {
            int d = du[cb];
            int ie = min(i, d - 1);
            int t = st[cb] + (dir ? (d - 1 - ie) : ie);
            const float* p = xbase + ((b0 + cb) * Tv + t) * 768;
            xr[cb] = p[g];
            xz[cb] = p[128 + g];
            xn[cb] = p[256 + g];
        }
        u64 ar0 = pk2(br, br), ar1 = ar0;
        u64 az0 = pk2(bz, bz), az1 = az0;
        u64 an0 = pk2(bn, bn), an1 = an0;
        #pragma unroll 4
        for (int k4 = 0; k4 < 32; k4++) {
            float4 wrq = *(const float4*)(wr + 4 * k4);
            float4 wzq = *(const float4*)(wz + 4 * k4);
            float4 wnq = *(const float4*)(wn + 4 * k4);
            float wrk[4] = {wrq.x, wrq.y, wrq.z, wrq.w};
            float wzk[4] = {wzq.x, wzq.y, wzq.z, wzq.w};
            float wnk[4] = {wnq.x, wnq.y, wnq.z, wnq.w};
            #pragma unroll
            for (int j = 0; j < 4; j++) {
                int k = 4 * k4 + j;
                ulonglong2 hp = *((const ulonglong2*)(h2 + k * 2));
                u64 wrp = pk2(wrk[j], wrk[j]);
                u64 wzp = pk2(wzk[j], wzk[j]);
                u64 wnp = pk2(wnk[j], wnk[j]);
                ar0 = fma2(wrp, hp.x, ar0);  ar1 = fma2(wrp, hp.y, ar1);
                az0 = fma2(wzp, hp.x, az0);  az1 = fma2(wzp, hp.y, az1);
                an0 = fma2(wnp, hp.x, an0);  an1 = fma2(wnp, hp.y, an1);
            }
        }
        float arf[4], azf[4], anf[4];
        up2(ar0, arf[0], arf[1]);  up2(ar1, arf[2], arf[3]);
        up2(az0, azf[0], azf[1]);  up2(az1, azf[2], azf[3]);
        up2(an0, anf[0], anf[1]);  up2(an1, anf[2], anf[3]);

        __syncthreads();   // all matvec reads of h2 complete

        #pragma unroll
        for (int cb = 0; cb < 4; cb++) {
            float rr = sigmoidf_fast(xr[cb] + arf[cb]);
            float zz = sigmoidf_fast(xz[cb] + azf[cb]);
            float n  = tanhf_fast(fmaf(rr, anf[cb], xn[cb]));
            float hv = fmaf(zz, hold[cb] - n, n);       // (1-z)*n + z*h
            if (i < du[cb]) hold[cb] = hv;              // freeze after segment end
        }
        h2[g * 2]     = pk2(hold[0], hold[1]);
        h2[g * 2 + 1] = pk2(hold[2], hold[3]);

        __syncthreads();   // h2 writes visible for next step
    }

    #pragma unroll
    for (int cb = 0; cb < 4; cb++) {
        int b = b0 + cb;
        float v = (s < src_len[b]) ? hold[cb] : 0.f;
        out[(b * Sv + s) * 256 + dir * 128 + g] = v;
    }
}

// ---------------------------------------------------------------------------
extern "C" void kernel_launch(void* const* d_in, const int* in_sizes, int n_in,
                              void* d_out, int out_size) {
    const float* mel      = (const float*)d_in[0];
    const int*   durations= (const int*)d_in[1];
    const int*   mel_len  = (const int*)d_in[2];
    const int*   src_len  = (const int*)d_in[3];
    const float* w1       = (const float*)d_in[4];
    const float* g1       = (const float*)d_in[5];
    const float* be1      = (const float*)d_in[6];
    const float* w2       = (const float*)d_in[7];
    const float* g2       = (const float*)d_in[8];
    const float* be2      = (const float*)d_in[9];
    const float* w_ih_f   = (const float*)d_in[10];
    const float* w_hh_f   = (const float*)d_in[11];
    const float* b_ih_f   = (const float*)d_in[12];
    const float* b_hh_f   = (const float*)d_in[13];
    const float* w_ih_b   = (const float*)d_in[14];
    const float* w_hh_b   = (const float*)d_in[15];
    const float* b_ih_b   = (const float*)d_in[16];
    const float* b_hh_b   = (const float*)d_in[17];
    float* out = (float*)d_out;

    size_t conv_smem = (size_t)(40 * PSW + 48) * sizeof(u64);
    size_t proj_smem = (size_t)(80 * PWW) * sizeof(u64) + (size_t)(80 * 66) * sizeof(float);
    size_t gru_smem  = (size_t)(384 * WSW) * sizeof(float) + 128 * 2 * sizeof(u64) + 16 * sizeof(int);
    cudaFuncSetAttribute(conv_kernel, cudaFuncAttributeMaxDynamicSharedMemorySize, (int)conv_smem);
    cudaFuncSetAttribute(proj_kernel, cudaFuncAttributeMaxDynamicSharedMemorySize, (int)proj_smem);
    cudaFuncSetAttribute(gru_kernel,  cudaFuncAttributeMaxDynamicSharedMemorySize, (int)gru_smem);

    conv_kernel<<<Bv * Tv, 128, conv_smem>>>(mel, mel_len, w1, g1, be1, w2, g2, be2);
    proj_kernel<<<dim3(150, 6), 256, proj_smem>>>(w_ih_f, b_ih_f, w_ih_b, b_ih_b);
    gru_kernel<<<400, 128, gru_smem>>>(durations, src_len, w_hh_f, b_hh_f, w_hh_b, b_hh_b, out);
}

// round 7
// speedup vs baseline: 1.3375x; 1.1111x over previous
#include <cuda_runtime.h>

#define Bv 8
#define Sv 100
#define Tv 1200
#define NMELv 80
#define DMv 128
#define KKv 9

typedef unsigned long long u64;

// Scratch (no cudaMalloc allowed)
__device__ float g_x[Bv * Tv * NMELv];          // conv output
__device__ float g_xg[Bv * Tv * 768];           // GRU input projections
__device__ int   g_start[Bv * Sv];              // segment starts (prefix sums)
__device__ int   g_ctr[2];                      // work-steal counters (per dir)

__device__ __forceinline__ float sigmoidf_fast(float x) {
    return __fdividef(1.f, 1.f + __expf(-x));
}
__device__ __forceinline__ float tanhf_fast(float x) {
    return 1.f - __fdividef(2.f, __expf(2.f * x) + 1.f);
}

// ---- packed f32x2 helpers (Blackwell sm_103a) ----
__device__ __forceinline__ u64 pk2(float lo, float hi) {
    u64 r; asm("mov.b64 %0, {%1, %2};" : "=l"(r) : "f"(lo), "f"(hi)); return r;
}
__device__ __forceinline__ void up2(u64 v, float& lo, float& hi) {
    asm("mov.b64 {%0, %1}, %2;" : "=f"(lo), "=f"(hi) : "l"(v));
}
__device__ __forceinline__ u64 fma2(u64 a, u64 b, u64 c) {
    u64 d; asm("fma.rn.f32x2 %0, %1, %2, %3;" : "=l"(d) : "l"(a), "l"(b), "l"(c)); return d;
}
__device__ __forceinline__ u64 add2(u64 a, u64 b) {
    u64 d; asm("add.rn.f32x2 %0, %1, %2;" : "=l"(d) : "l"(a), "l"(b)); return d;
}

#define PSW 134   // conv partial-row stride in u64 (1072 B, 16B-aligned rows)
#define WSW 132   // gru W row stride in floats (528 B, 16B-aligned rows, conflict-free)
#define PWW 130   // proj packed-W row stride in u64 (1040 B, 16B-aligned rows)

// ---------------------------------------------------------------------------
// Kernel 1: fused conv stack (round-5 version: best measured, 49.6us).
// ---------------------------------------------------------------------------
__global__ __launch_bounds__(128, 4) void conv_kernel(
    const float* __restrict__ mel, const int* __restrict__ mel_len,
    const float* __restrict__ w1, const float* __restrict__ g1, const float* __restrict__ be1,
    const float* __restrict__ w2, const float* __restrict__ g2, const float* __restrict__ be2)
{
    int bt = blockIdx.x;
    int b = bt / Tv, t = bt - b * Tv;
    if (t >= mel_len[b]) return;

    extern __shared__ __align__(16) float sm[];
    u64* ps2 = (u64*)sm;                   // [40][PSW] packed partials
    u64* mp2 = ps2 + 40 * PSW;             // 48 packed mel pairs
    int c = threadIdx.x;

    if (c < 48) {
        float lo = (c >= 4) ? mel[bt * NMELv + c - 4] : 0.f;
        float hi = (c < 44) ? mel[bt * NMELv + c + 36] : 0.f;
        mp2[c] = pk2(lo, hi);
    }

    float sc1c = g1[c] * rsqrtf(1.f + 1e-5f);
    float bb1c = be1[c];
    float s2   = g2[0] * rsqrtf(1.f + 1e-5f);
    u64 w1p[KKv], w2p[KKv];
    #pragma unroll
    for (int k = 0; k < KKv; k++) {
        float a = w1[c * KKv + k] * sc1c;  w1p[k] = pk2(a, a);
        float d = w2[c * KKv + k] * s2;    w2p[k] = pk2(d, d);
    }
    u64 bbp = pk2(bb1c, bb1c);
    __syncthreads();

    u64 Yp[48];
    u64 ring[9];
    #pragma unroll
    for (int j = 0; j < 8; j++) ring[j] = mp2[j];
    #pragma unroll
    for (int m = 0; m < 40; m++) {
        ring[(m + 8) % 9] = mp2[m + 8];
        u64 acc = bbp;
        #pragma unroll
        for (int k = 0; k < KKv; k++) acc = fma2(w1p[k], ring[(m + k) % 9], acc);
        float a, h; up2(acc, a, h);
        Yp[m + 4] = pk2(fmaxf(a, 0.f), fmaxf(h, 0.f));
    }
    #pragma unroll
    for (int j = 0; j < 4; j++) {
        float a, h;
        up2(Yp[40 + j], a, h); Yp[j]      = pk2(0.f, a);
        up2(Yp[4 + j],  a, h); Yp[44 + j] = pk2(h, 0.f);
    }

    #pragma unroll
    for (int m = 0; m < 40; m++) {
        u64 acc = 0ull;
        #pragma unroll
        for (int k = 0; k < KKv; k++) acc = fma2(w2p[k], Yp[m + k], acc);
        ps2[m * PSW + c] = acc;
    }
    __syncthreads();

    if (c < 40) {
        const ulonglong2* row = (const ulonglong2*)(ps2 + c * PSW);
        u64 s0 = 0ull, s1 = 0ull;
        #pragma unroll
        for (int q = 0; q < 32; q++) {
            ulonglong2 v0 = row[2 * q];
            ulonglong2 v1 = row[2 * q + 1];
            s0 = add2(s0, add2(v0.x, v0.y));
            s1 = add2(s1, add2(v1.x, v1.y));
        }
        u64 tot = add2(s0, s1);
        float a, h; up2(tot, a, h);
        float bb2 = be2[0];
        g_x[bt * NMELv + c]      = fmaxf(a + bb2, 0.f);
        g_x[bt * NMELv + c + 40] = fmaxf(h + bb2, 0.f);
    }
}

// ---------------------------------------------------------------------------
// Kernel 2: input projection GEMM, batch-aware grid (19, 6, 8) -> skip frames
// beyond mel_len[b]. Block (0,0,0) additionally computes segment starts and
// resets the gru work-steal counters (prep fold-in, saves a launch).
// ---------------------------------------------------------------------------
__global__ __launch_bounds__(256) void proj_kernel(
    const int* __restrict__ durations, const int* __restrict__ mel_len,
    const float* __restrict__ w_ih_f, const float* __restrict__ b_ih_f,
    const float* __restrict__ w_ih_b, const float* __restrict__ b_ih_b)
{
    int tid = threadIdx.x;
    int b   = blockIdx.z;
    int f0l = blockIdx.x * 64;
    int g0  = blockIdx.y * 128;

    // Prep fold-in: block (0,0,0) scans durations -> g_start, resets g_ctr.
    if (blockIdx.x == 0 && blockIdx.y == 0 && blockIdx.z == 0) {
        if (tid < 2) g_ctr[tid] = 0;
        int wid = tid >> 5, lane = tid & 31;
        if (wid < 8) {
            int carry = 0;
            #pragma unroll
            for (int c0 = 0; c0 < 128; c0 += 32) {
                int ss = c0 + lane;
                int d = (ss < Sv) ? durations[wid * Sv + ss] : 0;
                int v = d;
                #pragma unroll
                for (int off = 1; off < 32; off <<= 1) {
                    int n = __shfl_up_sync(0xFFFFFFFFu, v, off);
                    if (lane >= off) v += n;
                }
                if (ss < Sv) g_start[wid * Sv + ss] = carry + v - d;
                carry += __shfl_sync(0xFFFFFFFFu, v, 31);
            }
        }
    }

    if (f0l >= mel_len[b]) return;   // no segment reaches these frames

    extern __shared__ __align__(16) char smc[];
    u64*   Ws2 = (u64*)smc;                  // [80][PWW] duplicated pairs
    float* Xs  = (float*)(Ws2 + 80 * PWW);   // [80][66]

    for (int i = tid; i < 64 * NMELv; i += 256) {
        int r = i / NMELv, m = i - r * NMELv;
        int fr = min(f0l + r, Tv - 1);
        Xs[m * 66 + r] = g_x[(b * Tv + fr) * NMELv + m];
    }
    const float* wsrc = (g0 < 384) ? (w_ih_f + g0 * NMELv) : (w_ih_b + (g0 - 384) * NMELv);
    const float* bsrc = (g0 < 384) ? (b_ih_f + g0) : (b_ih_b + (g0 - 384));
    for (int i = tid; i < 128 * NMELv; i += 256) {
        int cc = i / NMELv, m = i - cc * NMELv;     // coalesced LDG
        float v = wsrc[i];
        Ws2[m * PWW + cc] = pk2(v, v);
    }
    __syncthreads();

    int tx = tid & 15, ty = tid >> 4;   // 8 gates x (2 frame-pairs) per thread
    u64 acc[8][2];
    #pragma unroll
    for (int u = 0; u < 8; u++) { acc[u][0] = 0ull; acc[u][1] = 0ull; }

    #pragma unroll 4
    for (int m = 0; m < NMELv; m++) {
        u64 x0 = *(const u64*)&Xs[m * 66 + ty * 4];
        u64 x1 = *(const u64*)&Xs[m * 66 + ty * 4 + 2];
        #pragma unroll
        for (int u = 0; u < 8; u++) {
            u64 wp = Ws2[m * PWW + tx + 16 * u];
            acc[u][0] = fma2(wp, x0, acc[u][0]);
            acc[u][1] = fma2(wp, x1, acc[u][1]);
        }
    }
    #pragma unroll
    for (int u = 0; u < 8; u++) {
        int cc = tx + 16 * u;
        float bias = bsrc[cc];
        float a[4];
        up2(acc[u][0], a[0], a[1]);
        up2(acc[u][1], a[2], a[3]);
        #pragma unroll
        for (int v = 0; v < 4; v++) {
            int rr = ty * 4 + v;
            if (f0l + rr < Tv)
                g_xg[(b * Tv + f0l + rr) * 768 + g0 + cc] = a[v] + bias;
        }
    }
}

// ---------------------------------------------------------------------------
// Kernel 3: segment GRU v7 — k-pair packing + persistent work stealing.
// 148 persistent blocks (dir = bid & 1). W loaded once per block into smem.
// Item = 4 chains (one (s, b-half)); 200 items/dir stolen via g_ctr.
// Inner loop: (w[k],w[k+1]) via LDS.128 from W rows (no pk2), (h[k],h[k+1])
// via broadcast LDS.128; horizontal add once per gate per step.
// ---------------------------------------------------------------------------
#define NITEMS 200
__global__ void __launch_bounds__(128, 1) gru_kernel(
    const int* __restrict__ durations, const int* __restrict__ src_len,
    const float* __restrict__ w_hh_f, const float* __restrict__ b_hh_f,
    const float* __restrict__ w_hh_b, const float* __restrict__ b_hh_b,
    float* __restrict__ out)
{
    int dir = blockIdx.x & 1;
    int g = threadIdx.x;                // 0..127 (hidden unit)

    extern __shared__ __align__(16) float smg[];
    float* Wt = smg;                    // [384][WSW]
    float* hs = Wt + 384 * WSW;         // [4][128] chain-major h
    int*  item_s = (int*)(hs + 4 * 128);

    // Load W once (vectorized, padded stride)
    const float* whh = dir ? w_hh_b : w_hh_f;
    {
        const float4* src = (const float4*)whh;
        for (int i = g; i < 384 * 32; i += 128) {
            int row = i >> 5, q = i & 31;
            *(float4*)&Wt[row * WSW + 4 * q] = src[i];
        }
    }
    const float* bhh = dir ? b_hh_b : b_hh_f;
    float br = bhh[g], bz = bhh[128 + g], bn = bhh[256 + g];
    const float* wr = Wt + g * WSW;
    const float* wz = Wt + (128 + g) * WSW;
    const float* wn = Wt + (256 + g) * WSW;
    const float* xbase = g_xg + dir * 384;

    for (;;) {
        __syncthreads();                            // protect item_s reuse
        if (g == 0) *item_s = atomicAdd(&g_ctr[dir], 1);
        __syncthreads();
        int item = *item_s;
        if (item >= NITEMS) break;

        int s = item >> 1, b0 = (item & 1) * 4;
        int st[4], du[4];
        #pragma unroll
        for (int cb = 0; cb < 4; cb++) {
            st[cb] = g_start[(b0 + cb) * Sv + s];
            du[cb] = durations[(b0 + cb) * Sv + s];
        }
        int maxd = max(max(du[0], du[1]), max(du[2], du[3]));

        float hold[4] = {0.f, 0.f, 0.f, 0.f};
        #pragma unroll
        for (int cb = 0; cb < 4; cb++) hs[cb * 128 + g] = 0.f;
        __syncthreads();

        for (int i = 0; i < maxd; i++) {
            // x projections: 3 gates x 4 chains (hidden under matvec)
            float xr[4], xz[4], xn4[4];
            #pragma unroll
            for (int cb = 0; cb < 4; cb++) {
                int d = du[cb];
                int ie = min(i, d - 1);
                int t = st[cb] + (dir ? (d - 1 - ie) : ie);
                const float* p = xbase + ((b0 + cb) * Tv + t) * 768;
                xr[cb] = p[g]; xz[cb] = p[128 + g]; xn4[cb] = p[256 + g];
            }
            u64 ar[4] = {0ull, 0ull, 0ull, 0ull};
            u64 az[4] = {0ull, 0ull, 0ull, 0ull};
            u64 an[4] = {0ull, 0ull, 0ull, 0ull};
            #pragma unroll 4
            for (int k4 = 0; k4 < 32; k4++) {
                ulonglong2 wrp = *(const ulonglong2*)(wr + 4 * k4);
                ulonglong2 wzp = *(const ulonglong2*)(wz + 4 * k4);
                ulonglong2 wnp = *(const ulonglong2*)(wn + 4 * k4);
                #pragma unroll
                for (int cb = 0; cb < 4; cb++) {
                    ulonglong2 hp = *(const ulonglong2*)(hs + cb * 128 + 4 * k4);
                    ar[cb] = fma2(wrp.x, hp.x, ar[cb]);
                    ar[cb] = fma2(wrp.y, hp.y, ar[cb]);
                    az[cb] = fma2(wzp.x, hp.x, az[cb]);
                    az[cb] = fma2(wzp.y, hp.y, az[cb]);
                    an[cb] = fma2(wnp.x, hp.x, an[cb]);
                    an[cb] = fma2(wnp.y, hp.y, an[cb]);
                }
            }
            __syncthreads();   // matvec reads of hs complete

            #pragma unroll
            for (int cb = 0; cb < 4; cb++) {
                float e0, e1;
                up2(ar[cb], e0, e1);
                float rr = sigmoidf_fast(xr[cb] + br + e0 + e1);
                up2(az[cb], e0, e1);
                float zz = sigmoidf_fast(xz[cb] + bz + e0 + e1);
                up2(an[cb], e0, e1);
                float nv = tanhf_fast(fmaf(rr, bn + e0 + e1, xn4[cb]));
                float hv = fmaf(zz, hold[cb] - nv, nv);    // (1-z)*n + z*h
                if (i < du[cb]) hold[cb] = hv;             // freeze after segment
                hs[cb * 128 + g] = hold[cb];
            }
            __syncthreads();   // hs writes visible
        }

        #pragma unroll
        for (int cb = 0; cb < 4; cb++) {
            int b = b0 + cb;
            float v = (s < src_len[b]) ? hold[cb] : 0.f;
            out[(b * Sv + s) * 256 + dir * 128 + g] = v;
        }
    }
}

// ---------------------------------------------------------------------------
extern "C" void kernel_launch(void* const* d_in, const int* in_sizes, int n_in,
                              void* d_out, int out_size) {
    const float* mel      = (const float*)d_in[0];
    const int*   durations= (const int*)d_in[1];
    const int*   mel_len  = (const int*)d_in[2];
    const int*   src_len  = (const int*)d_in[3];
    const float* w1       = (const float*)d_in[4];
    const float* g1       = (const float*)d_in[5];
    const float* be1      = (const float*)d_in[6];
    const float* w2       = (const float*)d_in[7];
    const float* g2       = (const float*)d_in[8];
    const float* be2      = (const float*)d_in[9];
    const float* w_ih_f   = (const float*)d_in[10];
    const float* w_hh_f   = (const float*)d_in[11];
    const float* b_ih_f   = (const float*)d_in[12];
    const float* b_hh_f   = (const float*)d_in[13];
    const float* w_ih_b   = (const float*)d_in[14];
    const float* w_hh_b   = (const float*)d_in[15];
    const float* b_ih_b   = (const float*)d_in[16];
    const float* b_hh_b   = (const float*)d_in[17];
    float* out = (float*)d_out;

    size_t conv_smem = (size_t)(40 * PSW + 48) * sizeof(u64);
    size_t proj_smem = (size_t)(80 * PWW) * sizeof(u64) + (size_t)(80 * 66) * sizeof(float);
    size_t gru_smem  = (size_t)(384 * WSW + 4 * 128) * sizeof(float) + 16;
    cudaFuncSetAttribute(conv_kernel, cudaFuncAttributeMaxDynamicSharedMemorySize, (int)conv_smem);
    cudaFuncSetAttribute(proj_kernel, cudaFuncAttributeMaxDynamicSharedMemorySize, (int)proj_smem);
    cudaFuncSetAttribute(gru_kernel,  cudaFuncAttributeMaxDynamicSharedMemorySize, (int)gru_smem);

    conv_kernel<<<Bv * Tv, 128, conv_smem>>>(mel, mel_len, w1, g1, be1, w2, g2, be2);
    proj_kernel<<<dim3(19, 6, 8), 256, proj_smem>>>(durations, mel_len,
                                                    w_ih_f, b_ih_f, w_ih_b, b_ih_b);
    gru_kernel<<<148, 128, gru_smem>>>(durations, src_len, w_hh_f, b_hh_f, w_hh_b, b_hh_b, out);
}

// round 8
// speedup vs baseline: 1.3380x; 1.0004x over previous
#include <cuda_runtime.h>

#define Bv 8
#define Sv 100
#define Tv 1200
#define NMELv 80
#define DMv 128
#define KKv 9

typedef unsigned long long u64;

// Scratch (no cudaMalloc allowed)
__device__ float g_x[Bv * Tv * NMELv];          // conv output
__device__ float g_xg[Bv * Tv * 768];           // GRU input projections
__device__ int   g_start[Bv * Sv];              // segment starts (prefix sums)
__device__ int   g_ctr[2];                      // work-steal counters (per dir)

__device__ __forceinline__ float sigmoidf_fast(float x) {
    return __fdividef(1.f, 1.f + __expf(-x));
}
__device__ __forceinline__ float tanhf_fast(float x) {
    return 1.f - __fdividef(2.f, __expf(2.f * x) + 1.f);
}

// ---- packed f32x2 helpers (Blackwell sm_103a) ----
__device__ __forceinline__ u64 pk2(float lo, float hi) {
    u64 r; asm("mov.b64 %0, {%1, %2};" : "=l"(r) : "f"(lo), "f"(hi)); return r;
}
__device__ __forceinline__ void up2(u64 v, float& lo, float& hi) {
    asm("mov.b64 {%0, %1}, %2;" : "=f"(lo), "=f"(hi) : "l"(v));
}
__device__ __forceinline__ u64 fma2(u64 a, u64 b, u64 c) {
    u64 d; asm("fma.rn.f32x2 %0, %1, %2, %3;" : "=l"(d) : "l"(a), "l"(b), "l"(c)); return d;
}
__device__ __forceinline__ u64 add2(u64 a, u64 b) {
    u64 d; asm("add.rn.f32x2 %0, %1, %2;" : "=l"(d) : "l"(a), "l"(b)); return d;
}

#define PSW 134   // conv partial-row stride in u64 (1072 B, 16B-aligned rows)
#define WSW 132   // gru W row stride in floats (528 B, 16B-aligned rows, conflict-free)
#define PWW 130   // proj packed-W row stride in u64 (1040 B, 16B-aligned rows)

// ---------------------------------------------------------------------------
// Kernel 1: fused conv stack (best measured config, 49.7us). Unchanged.
// ---------------------------------------------------------------------------
__global__ __launch_bounds__(128, 4) void conv_kernel(
    const float* __restrict__ mel, const int* __restrict__ mel_len,
    const float* __restrict__ w1, const float* __restrict__ g1, const float* __restrict__ be1,
    const float* __restrict__ w2, const float* __restrict__ g2, const float* __restrict__ be2)
{
    int bt = blockIdx.x;
    int b = bt / Tv, t = bt - b * Tv;
    if (t >= mel_len[b]) return;

    extern __shared__ __align__(16) float sm[];
    u64* ps2 = (u64*)sm;                   // [40][PSW] packed partials
    u64* mp2 = ps2 + 40 * PSW;             // 48 packed mel pairs
    int c = threadIdx.x;

    if (c < 48) {
        float lo = (c >= 4) ? mel[bt * NMELv + c - 4] : 0.f;
        float hi = (c < 44) ? mel[bt * NMELv + c + 36] : 0.f;
        mp2[c] = pk2(lo, hi);
    }

    float sc1c = g1[c] * rsqrtf(1.f + 1e-5f);
    float bb1c = be1[c];
    float s2   = g2[0] * rsqrtf(1.f + 1e-5f);
    u64 w1p[KKv], w2p[KKv];
    #pragma unroll
    for (int k = 0; k < KKv; k++) {
        float a = w1[c * KKv + k] * sc1c;  w1p[k] = pk2(a, a);
        float d = w2[c * KKv + k] * s2;    w2p[k] = pk2(d, d);
    }
    u64 bbp = pk2(bb1c, bb1c);
    __syncthreads();

    u64 Yp[48];
    u64 ring[9];
    #pragma unroll
    for (int j = 0; j < 8; j++) ring[j] = mp2[j];
    #pragma unroll
    for (int m = 0; m < 40; m++) {
        ring[(m + 8) % 9] = mp2[m + 8];
        u64 acc = bbp;
        #pragma unroll
        for (int k = 0; k < KKv; k++) acc = fma2(w1p[k], ring[(m + k) % 9], acc);
        float a, h; up2(acc, a, h);
        Yp[m + 4] = pk2(fmaxf(a, 0.f), fmaxf(h, 0.f));
    }
    #pragma unroll
    for (int j = 0; j < 4; j++) {
        float a, h;
        up2(Yp[40 + j], a, h); Yp[j]      = pk2(0.f, a);
        up2(Yp[4 + j],  a, h); Yp[44 + j] = pk2(h, 0.f);
    }

    #pragma unroll
    for (int m = 0; m < 40; m++) {
        u64 acc = 0ull;
        #pragma unroll
        for (int k = 0; k < KKv; k++) acc = fma2(w2p[k], Yp[m + k], acc);
        ps2[m * PSW + c] = acc;
    }
    __syncthreads();

    if (c < 40) {
        const ulonglong2* row = (const ulonglong2*)(ps2 + c * PSW);
        u64 s0 = 0ull, s1 = 0ull;
        #pragma unroll
        for (int q = 0; q < 32; q++) {
            ulonglong2 v0 = row[2 * q];
            ulonglong2 v1 = row[2 * q + 1];
            s0 = add2(s0, add2(v0.x, v0.y));
            s1 = add2(s1, add2(v1.x, v1.y));
        }
        u64 tot = add2(s0, s1);
        float a, h; up2(tot, a, h);
        float bb2 = be2[0];
        g_x[bt * NMELv + c]      = fmaxf(a + bb2, 0.f);
        g_x[bt * NMELv + c + 40] = fmaxf(h + bb2, 0.f);
    }
}

// ---------------------------------------------------------------------------
// Kernel 2: input projection GEMM, batch-aware grid; block (0,0,0) also does
// the segment-start prefix scans and resets the gru work-steal counters.
// ---------------------------------------------------------------------------
__global__ __launch_bounds__(256) void proj_kernel(
    const int* __restrict__ durations, const int* __restrict__ mel_len,
    const float* __restrict__ w_ih_f, const float* __restrict__ b_ih_f,
    const float* __restrict__ w_ih_b, const float* __restrict__ b_ih_b)
{
    int tid = threadIdx.x;
    int b   = blockIdx.z;
    int f0l = blockIdx.x * 64;
    int g0  = blockIdx.y * 128;

    if (blockIdx.x == 0 && blockIdx.y == 0 && blockIdx.z == 0) {
        if (tid < 2) g_ctr[tid] = 0;
        int wid = tid >> 5, lane = tid & 31;
        if (wid < 8) {
            int carry = 0;
            #pragma unroll
            for (int c0 = 0; c0 < 128; c0 += 32) {
                int ss = c0 + lane;
                int d = (ss < Sv) ? durations[wid * Sv + ss] : 0;
                int v = d;
                #pragma unroll
                for (int off = 1; off < 32; off <<= 1) {
                    int n = __shfl_up_sync(0xFFFFFFFFu, v, off);
                    if (lane >= off) v += n;
                }
                if (ss < Sv) g_start[wid * Sv + ss] = carry + v - d;
                carry += __shfl_sync(0xFFFFFFFFu, v, 31);
            }
        }
    }

    if (f0l >= mel_len[b]) return;

    extern __shared__ __align__(16) char smc[];
    u64*   Ws2 = (u64*)smc;                  // [80][PWW] duplicated pairs
    float* Xs  = (float*)(Ws2 + 80 * PWW);   // [80][66]

    for (int i = tid; i < 64 * NMELv; i += 256) {
        int r = i / NMELv, m = i - r * NMELv;
        int fr = min(f0l + r, Tv - 1);
        Xs[m * 66 + r] = g_x[(b * Tv + fr) * NMELv + m];
    }
    const float* wsrc = (g0 < 384) ? (w_ih_f + g0 * NMELv) : (w_ih_b + (g0 - 384) * NMELv);
    const float* bsrc = (g0 < 384) ? (b_ih_f + g0) : (b_ih_b + (g0 - 384));
    for (int i = tid; i < 128 * NMELv; i += 256) {
        int cc = i / NMELv, m = i - cc * NMELv;
        float v = wsrc[i];
        Ws2[m * PWW + cc] = pk2(v, v);
    }
    __syncthreads();

    int tx = tid & 15, ty = tid >> 4;
    u64 acc[8][2];
    #pragma unroll
    for (int u = 0; u < 8; u++) { acc[u][0] = 0ull; acc[u][1] = 0ull; }

    #pragma unroll 4
    for (int m = 0; m < NMELv; m++) {
        u64 x0 = *(const u64*)&Xs[m * 66 + ty * 4];
        u64 x1 = *(const u64*)&Xs[m * 66 + ty * 4 + 2];
        #pragma unroll
        for (int u = 0; u < 8; u++) {
            u64 wp = Ws2[m * PWW + tx + 16 * u];
            acc[u][0] = fma2(wp, x0, acc[u][0]);
            acc[u][1] = fma2(wp, x1, acc[u][1]);
        }
    }
    #pragma unroll
    for (int u = 0; u < 8; u++) {
        int cc = tx + 16 * u;
        float bias = bsrc[cc];
        float a[4];
        up2(acc[u][0], a[0], a[1]);
        up2(acc[u][1], a[2], a[3]);
        #pragma unroll
        for (int v = 0; v < 4; v++) {
            int rr = ty * 4 + v;
            if (f0l + rr < Tv)
                g_xg[(b * Tv + f0l + rr) * 768 + g0 + cc] = a[v] + bias;
        }
    }
}

// ---------------------------------------------------------------------------
// Kernel 3: segment GRU v8 — 8-chain items, dual 128-thread stealers/block.
// Item = (s, all 8 batches); 100 items/dir over 148 stealers/dir.
// W shared per block (one dir per block, dir = bid & 1); named barriers per half.
// Inner loop: W k-pairs via LDS.128 (own row), h via broadcast LDS.128,
// 48 fma2 per k4 -> fma-bound, not crossbar-bound.
// ---------------------------------------------------------------------------
#define NITEMS 100
__global__ void __launch_bounds__(256, 1) gru_kernel(
    const int* __restrict__ durations, const int* __restrict__ src_len,
    const float* __restrict__ w_hh_f, const float* __restrict__ b_hh_f,
    const float* __restrict__ w_hh_b, const float* __restrict__ b_hh_b,
    float* __restrict__ out)
{
    int dir = blockIdx.x & 1;
    int tid = threadIdx.x;
    int half = tid >> 7;                // two independent stealers
    int g = tid & 127;                  // hidden unit

    extern __shared__ __align__(16) float smg[];
    float* Wt = smg;                        // [384][WSW]
    float* hs = Wt + 384 * WSW;             // [2][8][128] chain-major h
    int* itemS = (int*)(hs + 2 * 8 * 128);  // [2]

    // Load W once (all 256 threads)
    const float* whh = dir ? w_hh_b : w_hh_f;
    {
        const float4* src = (const float4*)whh;
        for (int i = tid; i < 384 * 32; i += 256) {
            int row = i >> 5, q = i & 31;
            *(float4*)&Wt[row * WSW + 4 * q] = src[i];
        }
    }
    __syncthreads();

    const float* bhh = dir ? b_hh_b : b_hh_f;
    float br = bhh[g], bz = bhh[128 + g], bn = bhh[256 + g];
    const float* wr = Wt + g * WSW;
    const float* wz = Wt + (128 + g) * WSW;
    const float* wn = Wt + (256 + g) * WSW;
    const float* xbase = g_xg + dir * 384;
    float* hh = hs + half * 8 * 128;
    int barid = 1 + half;

    for (;;) {
        asm volatile("bar.sync %0, 128;" :: "r"(barid) : "memory");
        if (g == 0) itemS[half] = atomicAdd(&g_ctr[dir], 1);
        asm volatile("bar.sync %0, 128;" :: "r"(barid) : "memory");
        int s = itemS[half];
        if (s >= NITEMS) break;

        int st[8], du[8];
        int maxd = 0;
        #pragma unroll
        for (int cb = 0; cb < 8; cb++) {
            st[cb] = g_start[cb * Sv + s];
            du[cb] = durations[cb * Sv + s];
            maxd = max(maxd, du[cb]);
        }
        float hold[8];
        #pragma unroll
        for (int cb = 0; cb < 8; cb++) { hold[cb] = 0.f; hh[cb * 128 + g] = 0.f; }
        asm volatile("bar.sync %0, 128;" :: "r"(barid) : "memory");

        for (int i = 0; i < maxd; i++) {
            // x projections: 3 gates x 8 chains (independent LDGs, hidden under matvec)
            float xr[8], xz[8], xn4[8];
            #pragma unroll
            for (int cb = 0; cb < 8; cb++) {
                int d = du[cb];
                int ie = min(i, d - 1);
                int t = st[cb] + (dir ? (d - 1 - ie) : ie);
                const float* p = xbase + (cb * Tv + t) * 768;
                xr[cb] = p[g]; xz[cb] = p[128 + g]; xn4[cb] = p[256 + g];
            }
            u64 ar[8], az[8], an[8];
            #pragma unroll
            for (int cb = 0; cb < 8; cb++) { ar[cb] = 0ull; az[cb] = 0ull; an[cb] = 0ull; }
            #pragma unroll 2
            for (int k4 = 0; k4 < 32; k4++) {
                ulonglong2 wrp = *(const ulonglong2*)(wr + 4 * k4);
                ulonglong2 wzp = *(const ulonglong2*)(wz + 4 * k4);
                ulonglong2 wnp = *(const ulonglong2*)(wn + 4 * k4);
                #pragma unroll
                for (int cb = 0; cb < 8; cb++) {
                    ulonglong2 hp = *(const ulonglong2*)(hh + cb * 128 + 4 * k4);
                    ar[cb] = fma2(wrp.x, hp.x, ar[cb]);
                    ar[cb] = fma2(wrp.y, hp.y, ar[cb]);
                    az[cb] = fma2(wzp.x, hp.x, az[cb]);
                    az[cb] = fma2(wzp.y, hp.y, az[cb]);
                    an[cb] = fma2(wnp.x, hp.x, an[cb]);
                    an[cb] = fma2(wnp.y, hp.y, an[cb]);
                }
            }
            asm volatile("bar.sync %0, 128;" :: "r"(barid) : "memory");   // matvec reads done
            #pragma unroll
            for (int cb = 0; cb < 8; cb++) {
                float e0, e1;
                up2(ar[cb], e0, e1);
                float rr = sigmoidf_fast(xr[cb] + br + e0 + e1);
                up2(az[cb], e0, e1);
                float zz = sigmoidf_fast(xz[cb] + bz + e0 + e1);
                up2(an[cb], e0, e1);
                float nv = tanhf_fast(fmaf(rr, bn + e0 + e1, xn4[cb]));
                float hv = fmaf(zz, hold[cb] - nv, nv);     // (1-z)*n + z*h
                if (i < du[cb]) hold[cb] = hv;              // freeze after segment end
                hh[cb * 128 + g] = hold[cb];
            }
            asm volatile("bar.sync %0, 128;" :: "r"(barid) : "memory");   // h visible
        }

        #pragma unroll
        for (int cb = 0; cb < 8; cb++) {
            float v = (s < src_len[cb]) ? hold[cb] : 0.f;
            out[(cb * Sv + s) * 256 + dir * 128 + g] = v;
        }
    }
}

// ---------------------------------------------------------------------------
extern "C" void kernel_launch(void* const* d_in, const int* in_sizes, int n_in,
                              void* d_out, int out_size) {
    const float* mel      = (const float*)d_in[0];
    const int*   durations= (const int*)d_in[1];
    const int*   mel_len  = (const int*)d_in[2];
    const int*   src_len  = (const int*)d_in[3];
    const float* w1       = (const float*)d_in[4];
    const float* g1       = (const float*)d_in[5];
    const float* be1      = (const float*)d_in[6];
    const float* w2       = (const float*)d_in[7];
    const float* g2       = (const float*)d_in[8];
    const float* be2      = (const float*)d_in[9];
    const float* w_ih_f   = (const float*)d_in[10];
    const float* w_hh_f   = (const float*)d_in[11];
    const float* b_ih_f   = (const float*)d_in[12];
    const float* b_hh_f   = (const float*)d_in[13];
    const float* w_ih_b   = (const float*)d_in[14];
    const float* w_hh_b   = (const float*)d_in[15];
    const float* b_ih_b   = (const float*)d_in[16];
    const float* b_hh_b   = (const float*)d_in[17];
    float* out = (float*)d_out;

    size_t conv_smem = (size_t)(40 * PSW + 48) * sizeof(u64);
    size_t proj_smem = (size_t)(80 * PWW) * sizeof(u64) + (size_t)(80 * 66) * sizeof(float);
    size_t gru_smem  = (size_t)(384 * WSW + 2 * 8 * 128) * sizeof(float) + 8;
    cudaFuncSetAttribute(conv_kernel, cudaFuncAttributeMaxDynamicSharedMemorySize, (int)conv_smem);
    cudaFuncSetAttribute(proj_kernel, cudaFuncAttributeMaxDynamicSharedMemorySize, (int)proj_smem);
    cudaFuncSetAttribute(gru_kernel,  cudaFuncAttributeMaxDynamicSharedMemorySize, (int)gru_smem);

    conv_kernel<<<Bv * Tv, 128, conv_smem>>>(mel, mel_len, w1, g1, be1, w2, g2, be2);
    proj_kernel<<<dim3(19, 6, 8), 256, proj_smem>>>(durations, mel_len,
                                                    w_ih_f, b_ih_f, w_ih_b, b_ih_b);
    gru_kernel<<<148, 256, gru_smem>>>(durations, src_len, w_hh_f, b_hh_f, w_hh_b, b_hh_b, out);
}

// round 9
// speedup vs baseline: 1.3539x; 1.0119x over previous
#include <cuda_runtime.h>

#define Bv 8
#define Sv 100
#define Tv 1200
#define NMELv 80
#define DMv 128
#define KKv 9

typedef unsigned long long u64;

// Scratch (no cudaMalloc allowed)
__device__ float g_x[Bv * Tv * NMELv];          // conv output
__device__ float g_xg[Bv * Tv * 768];           // GRU input projections
__device__ int   g_start[Bv * Sv];              // segment starts (prefix sums)
__device__ int   g_sorted[Bv * Sv];             // chain ids sorted by duration desc
__device__ int   g_ctr[2];                      // work-steal counters (per dir)

__device__ __forceinline__ float sigmoidf_fast(float x) {
    return __fdividef(1.f, 1.f + __expf(-x));
}
__device__ __forceinline__ float tanhf_fast(float x) {
    return 1.f - __fdividef(2.f, __expf(2.f * x) + 1.f);
}

// ---- packed f32x2 helpers (Blackwell sm_103a) ----
__device__ __forceinline__ u64 pk2(float lo, float hi) {
    u64 r; asm("mov.b64 %0, {%1, %2};" : "=l"(r) : "f"(lo), "f"(hi)); return r;
}
__device__ __forceinline__ void up2(u64 v, float& lo, float& hi) {
    asm("mov.b64 {%0, %1}, %2;" : "=f"(lo), "=f"(hi) : "l"(v));
}
__device__ __forceinline__ u64 fma2(u64 a, u64 b, u64 c) {
    u64 d; asm("fma.rn.f32x2 %0, %1, %2, %3;" : "=l"(d) : "l"(a), "l"(b), "l"(c)); return d;
}
__device__ __forceinline__ u64 add2(u64 a, u64 b) {
    u64 d; asm("add.rn.f32x2 %0, %1, %2;" : "=l"(d) : "l"(a), "l"(b)); return d;
}

#define PSW 134   // conv partial-row stride in u64 (1072 B, 16B-aligned rows)
#define WSW 132   // gru W row stride in floats (528 B, 16B-aligned rows, conflict-free)
#define PWW 130   // proj packed-W row stride in u64 (1040 B, 16B-aligned rows)

// ---------------------------------------------------------------------------
// Kernel 1: fused conv stack (best measured config). Unchanged — control.
// ---------------------------------------------------------------------------
__global__ __launch_bounds__(128, 4) void conv_kernel(
    const float* __restrict__ mel, const int* __restrict__ mel_len,
    const float* __restrict__ w1, const float* __restrict__ g1, const float* __restrict__ be1,
    const float* __restrict__ w2, const float* __restrict__ g2, const float* __restrict__ be2)
{
    int bt = blockIdx.x;
    int b = bt / Tv, t = bt - b * Tv;
    if (t >= mel_len[b]) return;

    extern __shared__ __align__(16) float sm[];
    u64* ps2 = (u64*)sm;                   // [40][PSW] packed partials
    u64* mp2 = ps2 + 40 * PSW;             // 48 packed mel pairs
    int c = threadIdx.x;

    if (c < 48) {
        float lo = (c >= 4) ? mel[bt * NMELv + c - 4] : 0.f;
        float hi = (c < 44) ? mel[bt * NMELv + c + 36] : 0.f;
        mp2[c] = pk2(lo, hi);
    }

    float sc1c = g1[c] * rsqrtf(1.f + 1e-5f);
    float bb1c = be1[c];
    float s2   = g2[0] * rsqrtf(1.f + 1e-5f);
    u64 w1p[KKv], w2p[KKv];
    #pragma unroll
    for (int k = 0; k < KKv; k++) {
        float a = w1[c * KKv + k] * sc1c;  w1p[k] = pk2(a, a);
        float d = w2[c * KKv + k] * s2;    w2p[k] = pk2(d, d);
    }
    u64 bbp = pk2(bb1c, bb1c);
    __syncthreads();

    u64 Yp[48];
    u64 ring[9];
    #pragma unroll
    for (int j = 0; j < 8; j++) ring[j] = mp2[j];
    #pragma unroll
    for (int m = 0; m < 40; m++) {
        ring[(m + 8) % 9] = mp2[m + 8];
        u64 acc = bbp;
        #pragma unroll
        for (int k = 0; k < KKv; k++) acc = fma2(w1p[k], ring[(m + k) % 9], acc);
        float a, h; up2(acc, a, h);
        Yp[m + 4] = pk2(fmaxf(a, 0.f), fmaxf(h, 0.f));
    }
    #pragma unroll
    for (int j = 0; j < 4; j++) {
        float a, h;
        up2(Yp[40 + j], a, h); Yp[j]      = pk2(0.f, a);
        up2(Yp[4 + j],  a, h); Yp[44 + j] = pk2(h, 0.f);
    }

    #pragma unroll
    for (int m = 0; m < 40; m++) {
        u64 acc = 0ull;
        #pragma unroll
        for (int k = 0; k < KKv; k++) acc = fma2(w2p[k], Yp[m + k], acc);
        ps2[m * PSW + c] = acc;
    }
    __syncthreads();

    if (c < 40) {
        const ulonglong2* row = (const ulonglong2*)(ps2 + c * PSW);
        u64 s0 = 0ull, s1 = 0ull;
        #pragma unroll
        for (int q = 0; q < 32; q++) {
            ulonglong2 v0 = row[2 * q];
            ulonglong2 v1 = row[2 * q + 1];
            s0 = add2(s0, add2(v0.x, v0.y));
            s1 = add2(s1, add2(v1.x, v1.y));
        }
        u64 tot = add2(s0, s1);
        float a, h; up2(tot, a, h);
        float bb2 = be2[0];
        g_x[bt * NMELv + c]      = fmaxf(a + bb2, 0.f);
        g_x[bt * NMELv + c + 40] = fmaxf(h + bb2, 0.f);
    }
}

// ---------------------------------------------------------------------------
// Kernel 2: input projection GEMM; block (0,0,0) also does prep:
// segment-start prefix scans, duration counting-sort (descending -> LPT),
// and gru counter reset.
// ---------------------------------------------------------------------------
__global__ __launch_bounds__(256) void proj_kernel(
    const int* __restrict__ durations, const int* __restrict__ mel_len,
    const float* __restrict__ w_ih_f, const float* __restrict__ b_ih_f,
    const float* __restrict__ w_ih_b, const float* __restrict__ b_ih_b)
{
    int tid = threadIdx.x;
    int b   = blockIdx.z;
    int f0l = blockIdx.x * 64;
    int g0  = blockIdx.y * 128;

    if (blockIdx.x == 0 && blockIdx.y == 0 && blockIdx.z == 0) {
        __shared__ int bcnt[9], boff[9];
        if (tid < 2) g_ctr[tid] = 0;
        if (tid < 9) bcnt[tid] = 0;
        // prefix scans -> g_start
        int wid = tid >> 5, lane = tid & 31;
        if (wid < 8) {
            int carry = 0;
            #pragma unroll
            for (int c0 = 0; c0 < 128; c0 += 32) {
                int ss = c0 + lane;
                int d = (ss < Sv) ? durations[wid * Sv + ss] : 0;
                int v = d;
                #pragma unroll
                for (int off = 1; off < 32; off <<= 1) {
                    int n = __shfl_up_sync(0xFFFFFFFFu, v, off);
                    if (lane >= off) v += n;
                }
                if (ss < Sv) g_start[wid * Sv + ss] = carry + v - d;
                carry += __shfl_sync(0xFFFFFFFFu, v, 31);
            }
        }
        __syncthreads();
        // counting sort by duration, DESCENDING (dur in [4,12] -> bin 12-d)
        for (int i = tid; i < Bv * Sv; i += 256)
            atomicAdd(&bcnt[12 - durations[i]], 1);
        __syncthreads();
        if (tid == 0) {
            int off = 0;
            for (int q = 0; q < 9; q++) { boff[q] = off; off += bcnt[q]; }
        }
        __syncthreads();
        for (int i = tid; i < Bv * Sv; i += 256) {
            int pos = atomicAdd(&boff[12 - durations[i]], 1);
            g_sorted[pos] = i;
        }
    }

    if (f0l >= mel_len[b]) return;

    extern __shared__ __align__(16) char smc[];
    u64*   Ws2 = (u64*)smc;                  // [80][PWW] duplicated pairs
    float* Xs  = (float*)(Ws2 + 80 * PWW);   // [80][66]

    for (int i = tid; i < 64 * NMELv; i += 256) {
        int r = i / NMELv, m = i - r * NMELv;
        int fr = min(f0l + r, Tv - 1);
        Xs[m * 66 + r] = g_x[(b * Tv + fr) * NMELv + m];
    }
    const float* wsrc = (g0 < 384) ? (w_ih_f + g0 * NMELv) : (w_ih_b + (g0 - 384) * NMELv);
    const float* bsrc = (g0 < 384) ? (b_ih_f + g0) : (b_ih_b + (g0 - 384));
    for (int i = tid; i < 128 * NMELv; i += 256) {
        int cc = i / NMELv, m = i - cc * NMELv;
        float v = wsrc[i];
        Ws2[m * PWW + cc] = pk2(v, v);
    }
    __syncthreads();

    int tx = tid & 15, ty = tid >> 4;
    u64 acc[8][2];
    #pragma unroll
    for (int u = 0; u < 8; u++) { acc[u][0] = 0ull; acc[u][1] = 0ull; }

    #pragma unroll 4
    for (int m = 0; m < NMELv; m++) {
        u64 x0 = *(const u64*)&Xs[m * 66 + ty * 4];
        u64 x1 = *(const u64*)&Xs[m * 66 + ty * 4 + 2];
        #pragma unroll
        for (int u = 0; u < 8; u++) {
            u64 wp = Ws2[m * PWW + tx + 16 * u];
            acc[u][0] = fma2(wp, x0, acc[u][0]);
            acc[u][1] = fma2(wp, x1, acc[u][1]);
        }
    }
    #pragma unroll
    for (int u = 0; u < 8; u++) {
        int cc = tx + 16 * u;
        float bias = bsrc[cc];
        float a[4];
        up2(acc[u][0], a[0], a[1]);
        up2(acc[u][1], a[2], a[3]);
        #pragma unroll
        for (int v = 0; v < 4; v++) {
            int rr = ty * 4 + v;
            if (f0l + rr < Tv)
                g_xg[(b * Tv + f0l + rr) * 768 + g0 + cc] = a[v] + bias;
        }
    }
}

// ---------------------------------------------------------------------------
// Kernel 3: segment GRU v9 — sorted 8-chain items (LPT), dual stealers/block.
// Items = 8 consecutive duration-sorted chains -> maxd ~ mean dur (padding
// tax 1.46x -> ~1.02x). 148 blocks, dir = bid & 1, W in smem per block.
// ---------------------------------------------------------------------------
#define NITEMS 100
__global__ void __launch_bounds__(256, 1) gru_kernel(
    const int* __restrict__ durations, const int* __restrict__ src_len,
    const float* __restrict__ w_hh_f, const float* __restrict__ b_hh_f,
    const float* __restrict__ w_hh_b, const float* __restrict__ b_hh_b,
    float* __restrict__ out)
{
    int dir = blockIdx.x & 1;
    int tid = threadIdx.x;
    int half = tid >> 7;                // two independent stealers
    int g = tid & 127;                  // hidden unit

    extern __shared__ __align__(16) float smg[];
    float* Wt = smg;                        // [384][WSW]
    float* hs = Wt + 384 * WSW;             // [2][8][128] chain-major h
    int* itemS = (int*)(hs + 2 * 8 * 128);  // [2]

    // Load W once (all 256 threads)
    const float* whh = dir ? w_hh_b : w_hh_f;
    {
        const float4* src = (const float4*)whh;
        for (int i = tid; i < 384 * 32; i += 256) {
            int row = i >> 5, q = i & 31;
            *(float4*)&Wt[row * WSW + 4 * q] = src[i];
        }
    }
    __syncthreads();

    const float* bhh = dir ? b_hh_b : b_hh_f;
    float br = bhh[g], bz = bhh[128 + g], bn = bhh[256 + g];
    const float* wr = Wt + g * WSW;
    const float* wz = Wt + (128 + g) * WSW;
    const float* wn = Wt + (256 + g) * WSW;
    const float* xbase = g_xg + dir * 384;
    float* hh = hs + half * 8 * 128;
    int barid = 1 + half;

    for (;;) {
        asm volatile("bar.sync %0, 128;" :: "r"(barid) : "memory");
        if (g == 0) itemS[half] = atomicAdd(&g_ctr[dir], 1);
        asm volatile("bar.sync %0, 128;" :: "r"(barid) : "memory");
        int item = itemS[half];
        if (item >= NITEMS) break;

        int ee[8], st[8], du[8], bt8[8];
        int maxd = 0;
        #pragma unroll
        for (int cb = 0; cb < 8; cb++) {
            int e = g_sorted[item * 8 + cb];
            ee[cb] = e;
            st[cb] = g_start[e];
            du[cb] = durations[e];
            bt8[cb] = (e / Sv) * Tv;
            maxd = max(maxd, du[cb]);
        }
        float hold[8];
        #pragma unroll
        for (int cb = 0; cb < 8; cb++) { hold[cb] = 0.f; hh[cb * 128 + g] = 0.f; }
        asm volatile("bar.sync %0, 128;" :: "r"(barid) : "memory");

        for (int i = 0; i < maxd; i++) {
            float xr[8], xz[8], xn4[8];
            #pragma unroll
            for (int cb = 0; cb < 8; cb++) {
                int d = du[cb];
                int ie = min(i, d - 1);
                int t = st[cb] + (dir ? (d - 1 - ie) : ie);
                const float* p = xbase + (bt8[cb] + t) * 768;
                xr[cb] = p[g]; xz[cb] = p[128 + g]; xn4[cb] = p[256 + g];
            }
            u64 ar[8], az[8], an[8];
            #pragma unroll
            for (int cb = 0; cb < 8; cb++) { ar[cb] = 0ull; az[cb] = 0ull; an[cb] = 0ull; }
            #pragma unroll 2
            for (int k4 = 0; k4 < 32; k4++) {
                ulonglong2 wrp = *(const ulonglong2*)(wr + 4 * k4);
                ulonglong2 wzp = *(const ulonglong2*)(wz + 4 * k4);
                ulonglong2 wnp = *(const ulonglong2*)(wn + 4 * k4);
                #pragma unroll
                for (int cb = 0; cb < 8; cb++) {
                    ulonglong2 hp = *(const ulonglong2*)(hh + cb * 128 + 4 * k4);
                    ar[cb] = fma2(wrp.x, hp.x, ar[cb]);
                    ar[cb] = fma2(wrp.y, hp.y, ar[cb]);
                    az[cb] = fma2(wzp.x, hp.x, az[cb]);
                    az[cb] = fma2(wzp.y, hp.y, az[cb]);
                    an[cb] = fma2(wnp.x, hp.x, an[cb]);
                    an[cb] = fma2(wnp.y, hp.y, an[cb]);
                }
            }
            asm volatile("bar.sync %0, 128;" :: "r"(barid) : "memory");   // matvec reads done
            #pragma unroll
            for (int cb = 0; cb < 8; cb++) {
                float e0, e1;
                up2(ar[cb], e0, e1);
                float rr = sigmoidf_fast(xr[cb] + br + e0 + e1);
                up2(az[cb], e0, e1);
                float zz = sigmoidf_fast(xz[cb] + bz + e0 + e1);
                up2(an[cb], e0, e1);
                float nv = tanhf_fast(fmaf(rr, bn + e0 + e1, xn4[cb]));
                float hv = fmaf(zz, hold[cb] - nv, nv);     // (1-z)*n + z*h
                if (i < du[cb]) hold[cb] = hv;              // freeze after segment end
                hh[cb * 128 + g] = hold[cb];
            }
            asm volatile("bar.sync %0, 128;" :: "r"(barid) : "memory");   // h visible
        }

        #pragma unroll
        for (int cb = 0; cb < 8; cb++) {
            int e = ee[cb];
            int bb = e / Sv, ss = e - bb * Sv;
            float v = (ss < src_len[bb]) ? hold[cb] : 0.f;
            out[e * 256 + dir * 128 + g] = v;
        }
    }
}

// ---------------------------------------------------------------------------
extern "C" void kernel_launch(void* const* d_in, const int* in_sizes, int n_in,
                              void* d_out, int out_size) {
    const float* mel      = (const float*)d_in[0];
    const int*   durations= (const int*)d_in[1];
    const int*   mel_len  = (const int*)d_in[2];
    const int*   src_len  = (const int*)d_in[3];
    const float* w1       = (const float*)d_in[4];
    const float* g1       = (const float*)d_in[5];
    const float* be1      = (const float*)d_in[6];
    const float* w2       = (const float*)d_in[7];
    const float* g2       = (const float*)d_in[8];
    const float* be2      = (const float*)d_in[9];
    const float* w_ih_f   = (const float*)d_in[10];
    const float* w_hh_f   = (const float*)d_in[11];
    const float* b_ih_f   = (const float*)d_in[12];
    const float* b_hh_f   = (const float*)d_in[13];
    const float* w_ih_b   = (const float*)d_in[14];
    const float* w_hh_b   = (const float*)d_in[15];
    const float* b_ih_b   = (const float*)d_in[16];
    const float* b_hh_b   = (const float*)d_in[17];
    float* out = (float*)d_out;

    size_t conv_smem = (size_t)(40 * PSW + 48) * sizeof(u64);
    size_t proj_smem = (size_t)(80 * PWW) * sizeof(u64) + (size_t)(80 * 66) * sizeof(float);
    size_t gru_smem  = (size_t)(384 * WSW + 2 * 8 * 128) * sizeof(float) + 8;
    cudaFuncSetAttribute(conv_kernel, cudaFuncAttributeMaxDynamicSharedMemorySize, (int)conv_smem);
    cudaFuncSetAttribute(proj_kernel, cudaFuncAttributeMaxDynamicSharedMemorySize, (int)proj_smem);
    cudaFuncSetAttribute(gru_kernel,  cudaFuncAttributeMaxDynamicSharedMemorySize, (int)gru_smem);

    conv_kernel<<<Bv * Tv, 128, conv_smem>>>(mel, mel_len, w1, g1, be1, w2, g2, be2);
    proj_kernel<<<dim3(19, 6, 8), 256, proj_smem>>>(durations, mel_len,
                                                    w_ih_f, b_ih_f, w_ih_b, b_ih_b);
    gru_kernel<<<148, 256, gru_smem>>>(durations, src_len, w_hh_f, b_hh_f, w_hh_b, b_hh_b, out);
}